// round 1
// baseline (speedup 1.0000x reference)
#include <cuda_runtime.h>
#include <cuda_bf16.h>
#include <math.h>

#define NN      20000
#define NE      320000
#define INDIM   128
#define HID     256
#define HEADS   8
#define DH      32
#define LAYERS  3
#define NG      64
#define OUTDIM  10
#define SLOPE   0.2f

// ---------------- scratch (device globals; no allocation allowed) ----------
__device__ float g_h[NN * HID];
__device__ float g_fs[NN * HID];
__device__ float g_fd[NN * HID];
__device__ float g_rst[NN * HID];
__device__ float g_score[NE * HEADS];
__device__ float g_m[NN * HEADS];
__device__ float g_denom[NN * HEADS];
__device__ float g_hg[NG * HID];
__device__ float g_x1[NG * HID];
__device__ float g_x2[NG * (HID / 2)];

// ---------------- helpers ---------------------------------------------------
__device__ __forceinline__ void atomicMaxFloat(float* addr, float val) {
    int* ai = reinterpret_cast<int*>(addr);
    int old = __float_as_int(*addr);
    while (__int_as_float(old) < val) {
        int assumed = old;
        old = atomicCAS(ai, assumed, __float_as_int(val));
        if (old == assumed) break;
    }
}

// ---------------- generic register-tiled fp32 GEMM: C = A@B + bias ----------
// A: [M,K] row-major, B: [K,N] row-major, bias: [N]. N%64==0, K%16==0 required.
#define BM 64
#define BN 64
#define BK 16
__global__ __launch_bounds__(256) void gemm_bias_kernel(
    const float* __restrict__ A, const float* __restrict__ B,
    const float* __restrict__ bias, float* __restrict__ C,
    int M, int N, int K)
{
    __shared__ float As[BK][BM + 4];
    __shared__ float Bs[BK][BN + 4];

    const int bx = blockIdx.x;   // N tile
    const int by = blockIdx.y;   // M tile
    const int tid = threadIdx.x;
    const int tx = tid & 15;     // 0..15
    const int ty = tid >> 4;     // 0..15
    const int row0 = by * BM + ty * 4;
    const int col0 = bx * BN + tx * 4;

    float acc[4][4] = {};

    for (int k0 = 0; k0 < K; k0 += BK) {
        // A tile: BM x BK (1024 elems, 4 per thread)
        #pragma unroll
        for (int i = 0; i < 4; i++) {
            int idx = tid + i * 256;
            int r = idx >> 4;           // /BK
            int c = idx & 15;           // %BK
            int gr = by * BM + r;
            As[c][r] = (gr < M) ? A[(size_t)gr * K + k0 + c] : 0.f;
        }
        // B tile: BK x BN
        #pragma unroll
        for (int i = 0; i < 4; i++) {
            int idx = tid + i * 256;
            int r = idx >> 6;           // /BN
            int c = idx & 63;           // %BN
            Bs[r][c] = B[(size_t)(k0 + r) * N + bx * BN + c];
        }
        __syncthreads();

        #pragma unroll
        for (int kk = 0; kk < BK; kk++) {
            float ar[4], br[4];
            #pragma unroll
            for (int i = 0; i < 4; i++) ar[i] = As[kk][ty * 4 + i];
            #pragma unroll
            for (int j = 0; j < 4; j++) br[j] = Bs[kk][tx * 4 + j];
            #pragma unroll
            for (int i = 0; i < 4; i++)
                #pragma unroll
                for (int j = 0; j < 4; j++)
                    acc[i][j] = fmaf(ar[i], br[j], acc[i][j]);
        }
        __syncthreads();
    }

    #pragma unroll
    for (int i = 0; i < 4; i++) {
        int r = row0 + i;
        if (r < M) {
            #pragma unroll
            for (int j = 0; j < 4; j++)
                C[(size_t)r * N + col0 + j] = acc[i][j] + bias[col0 + j];
        }
    }
}

// ---------------- per-layer init: rst=0, m=-inf, denom=0 --------------------
__global__ void init_layer_kernel() {
    int i = blockIdx.x * blockDim.x + threadIdx.x;
    if (i < NN * HID) g_rst[i] = 0.f;
    if (i < NN * HEADS) { g_m[i] = -1e30f; g_denom[i] = 0.f; }
}

// ---------------- edge scores + segment max (one warp per edge) -------------
__global__ void edge_score_kernel(const int* __restrict__ src,
                                  const int* __restrict__ dst,
                                  const float* __restrict__ attn /* [HEADS*DH] */)
{
    int warp = (blockIdx.x * blockDim.x + threadIdx.x) >> 5;
    int lane = threadIdx.x & 31;
    if (warp >= NE) return;
    int s = src[warp];
    int d = dst[warp];
    const float* fsrow = g_fs + (size_t)s * HID;
    const float* fdrow = g_fd + (size_t)d * HID;
    #pragma unroll
    for (int h = 0; h < HEADS; h++) {
        float v = fsrow[h * DH + lane] + fdrow[h * DH + lane];
        v = (v > 0.f) ? v : SLOPE * v;
        float p = v * attn[h * DH + lane];
        #pragma unroll
        for (int o = 16; o; o >>= 1) p += __shfl_xor_sync(0xffffffffu, p, o);
        if (lane == 0) {
            g_score[(size_t)warp * HEADS + h] = p;
            atomicMaxFloat(&g_m[d * HEADS + h], p);
        }
    }
}

// ---------------- exp + denom accumulation ----------------------------------
__global__ void edge_exp_kernel(const int* __restrict__ dst) {
    int i = blockIdx.x * blockDim.x + threadIdx.x;
    if (i >= NE * HEADS) return;
    int e = i >> 3;      // /HEADS
    int h = i & 7;       // %HEADS
    int d = dst[e];
    float ex = expf(g_score[i] - g_m[d * HEADS + h]);
    g_score[i] = ex;
    atomicAdd(&g_denom[d * HEADS + h], ex);
}

// ---------------- alpha * fs[src] scatter (one warp per edge) ---------------
__global__ void edge_scatter_kernel(const int* __restrict__ src,
                                    const int* __restrict__ dst)
{
    int warp = (blockIdx.x * blockDim.x + threadIdx.x) >> 5;
    int lane = threadIdx.x & 31;
    if (warp >= NE) return;
    int s = src[warp];
    int d = dst[warp];
    const float* fsrow = g_fs + (size_t)s * HID;
    float* rrow = g_rst + (size_t)d * HID;
    #pragma unroll
    for (int h = 0; h < HEADS; h++) {
        float alpha = g_score[(size_t)warp * HEADS + h] / g_denom[d * HEADS + h];
        float val = alpha * fsrow[h * DH + lane];
        atomicAdd(&rrow[h * DH + lane], val);
    }
}

// ---------------- residual + relu: h = relu(rst + h) ------------------------
__global__ void residual_relu_kernel() {
    int i = blockIdx.x * blockDim.x + threadIdx.x;
    if (i >= NN * HID) return;
    g_h[i] = fmaxf(g_rst[i] + g_h[i], 0.f);
}

// ---------------- graph sum pooling ------------------------------------------
__global__ void zero_hg_kernel() {
    int i = blockIdx.x * blockDim.x + threadIdx.x;
    if (i < NG * HID) g_hg[i] = 0.f;
}

__global__ void pool_kernel(const int* __restrict__ graph_ids) {
    int i = blockIdx.x * blockDim.x + threadIdx.x;
    if (i >= NN * HID) return;
    int n = i >> 8;       // /HID
    int c = i & 255;      // %HID
    atomicAdd(&g_hg[graph_ids[n] * HID + c], g_h[i]);
}

// ---------------- small FC: Y = act(X@W + b) ---------------------------------
// grid = M blocks, block = 256 threads. K <= 256, N <= 256.
__global__ void fc_kernel(const float* __restrict__ X, const float* __restrict__ W,
                          const float* __restrict__ b, float* __restrict__ Y,
                          int N, int K, int do_relu)
{
    __shared__ float xs[256];
    int row = blockIdx.x;
    for (int i = threadIdx.x; i < K; i += blockDim.x) xs[i] = X[row * K + i];
    __syncthreads();
    int col = threadIdx.x;
    if (col < N) {
        float s = b[col];
        for (int k = 0; k < K; k++) s = fmaf(xs[k], W[k * N + col], s);
        if (do_relu) s = fmaxf(s, 0.f);
        Y[row * N + col] = s;
    }
}

// ---------------- launch -----------------------------------------------------
extern "C" void kernel_launch(void* const* d_in, const int* in_sizes, int n_in,
                              void* d_out, int out_size)
{
    const float* feature   = (const float*)d_in[0];
    const float* W_in      = (const float*)d_in[1];
    const float* b_in      = (const float*)d_in[2];
    const float* W_src     = (const float*)d_in[3];   // [L,HID,HID]
    const float* b_src     = (const float*)d_in[4];   // [L,HID]
    const float* W_dst     = (const float*)d_in[5];
    const float* b_dst     = (const float*)d_in[6];
    const float* attn      = (const float*)d_in[7];   // [L,HEADS,DH]
    const float* Wc1       = (const float*)d_in[8];
    const float* bc1       = (const float*)d_in[9];
    const float* Wc2       = (const float*)d_in[10];
    const float* bc2       = (const float*)d_in[11];
    const float* Wc3       = (const float*)d_in[12];
    const float* bc3       = (const float*)d_in[13];
    const int*   src       = (const int*)d_in[14];
    const int*   dst       = (const int*)d_in[15];
    const int*   graph_ids = (const int*)d_in[16];
    float* out = (float*)d_out;

    float *p_h, *p_fs, *p_fd, *p_hg, *p_x1, *p_x2;
    cudaGetSymbolAddress((void**)&p_h,  g_h);
    cudaGetSymbolAddress((void**)&p_fs, g_fs);
    cudaGetSymbolAddress((void**)&p_fd, g_fd);
    cudaGetSymbolAddress((void**)&p_hg, g_hg);
    cudaGetSymbolAddress((void**)&p_x1, g_x1);
    cudaGetSymbolAddress((void**)&p_x2, g_x2);

    dim3 ggrid(HID / BN, (NN + BM - 1) / BM);

    // h = feature @ W_in + b_in
    gemm_bias_kernel<<<ggrid, 256>>>(feature, W_in, b_in, p_h, NN, HID, INDIM);

    const int ethreads = 256;
    const int escore_blocks = (NE * 32 + ethreads - 1) / ethreads;  // warp per edge
    const int init_blocks = (NN * HID + 255) / 256;
    const int expe_blocks = (NE * HEADS + 255) / 256;

    for (int l = 0; l < LAYERS; l++) {
        const float* Ws = W_src + (size_t)l * HID * HID;
        const float* bs = b_src + (size_t)l * HID;
        const float* Wd = W_dst + (size_t)l * HID * HID;
        const float* bd = b_dst + (size_t)l * HID;
        const float* al = attn + (size_t)l * HEADS * DH;

        gemm_bias_kernel<<<ggrid, 256>>>(p_h, Ws, bs, p_fs, NN, HID, HID);
        gemm_bias_kernel<<<ggrid, 256>>>(p_h, Wd, bd, p_fd, NN, HID, HID);
        init_layer_kernel<<<init_blocks, 256>>>();
        edge_score_kernel<<<escore_blocks, ethreads>>>(src, dst, al);
        edge_exp_kernel<<<expe_blocks, 256>>>(dst);
        edge_scatter_kernel<<<escore_blocks, ethreads>>>(src, dst);
        residual_relu_kernel<<<init_blocks, 256>>>();
    }

    zero_hg_kernel<<<(NG * HID + 255) / 256, 256>>>();
    pool_kernel<<<init_blocks, 256>>>(graph_ids);

    fc_kernel<<<NG, 256>>>(p_hg, Wc1, bc1, p_x1, HID, HID, 1);
    fc_kernel<<<NG, 256>>>(p_x1, Wc2, bc2, p_x2, HID / 2, HID, 1);
    fc_kernel<<<NG, 256>>>(p_x2, Wc3, bc3, out, OUTDIM, HID / 2, 0);
}

// round 2
// speedup vs baseline: 1.2478x; 1.2478x over previous
#include <cuda_runtime.h>
#include <cuda_bf16.h>
#include <math.h>

#define NN      20000
#define NE      320000
#define INDIM   128
#define HID     256
#define HEADS   8
#define DH      32
#define LAYERS  3
#define NG      64
#define OUTDIM  10
#define SLOPE   0.2f

// ---------------- scratch (device globals; no allocation allowed) ----------
__device__ float g_h[NN * HID];
__device__ float g_fs[NN * HID];
__device__ float g_fd[NN * HID];
__device__ float g_score[NE * HEADS];
__device__ float g_m[NN * HEADS];
__device__ float g_inv[NN * HEADS];
__device__ float g_hg[NG * HID];
__device__ float g_x1[NG * HID];
__device__ float g_x2[NG * (HID / 2)];
// CSR by dst
__device__ int g_cnt[NN];
__device__ int g_base[NN + 1];
__device__ int g_cur[NN];
__device__ int g_ebyd[NE];

// ---------------- tf32 helpers ----------------------------------------------
__device__ __forceinline__ unsigned cvt_tf32(float x) {
    unsigned r;
    asm("cvt.rna.tf32.f32 %0, %1;" : "=r"(r) : "f"(x));
    return r;
}

__device__ __forceinline__ void mma_tf32(float c[4], const unsigned a[4], const unsigned b[2]) {
    asm volatile(
        "mma.sync.aligned.m16n8k8.row.col.f32.tf32.tf32.f32 "
        "{%0,%1,%2,%3}, {%4,%5,%6,%7}, {%8,%9}, {%0,%1,%2,%3};"
        : "+f"(c[0]), "+f"(c[1]), "+f"(c[2]), "+f"(c[3])
        : "r"(a[0]), "r"(a[1]), "r"(a[2]), "r"(a[3]), "r"(b[0]), "r"(b[1]));
}

// ---------------- tensor-core GEMM (3xTF32 split, fp32-accurate) ------------
// C[M,N] = A[M,K] @ B[K,N] + bias[N].  K%16==0, N%128==0.
#define GBM 128
#define GBN 128
#define GBK 16

__global__ __launch_bounds__(256) void gemm_tf32_kernel(
    const float* __restrict__ A, const float* __restrict__ B,
    const float* __restrict__ bias, float* __restrict__ C,
    int M, int N, int K)
{
    __shared__ unsigned As_hi[GBM][GBK + 4];   // stride 20: frag loads conflict-free
    __shared__ unsigned As_lo[GBM][GBK + 4];
    __shared__ unsigned Bs_hi[GBK][GBN + 8];   // stride 136: frag loads conflict-free
    __shared__ unsigned Bs_lo[GBK][GBN + 8];

    const int tid  = threadIdx.x;
    const int wid  = tid >> 5;
    const int lane = tid & 31;
    const int wm   = (wid >> 2) * 64;       // warp m offset (0,64)
    const int wn   = (wid & 3) * 32;        // warp n offset (0..96)
    const int grp  = lane >> 2;             // 0..7
    const int tig  = lane & 3;              // 0..3
    const int row0 = blockIdx.y * GBM;
    const int col0 = blockIdx.x * GBN;

    float c[4][4][4];
    #pragma unroll
    for (int i = 0; i < 4; i++)
        #pragma unroll
        for (int j = 0; j < 4; j++)
            #pragma unroll
            for (int k = 0; k < 4; k++) c[i][j][k] = 0.f;

    for (int k0 = 0; k0 < K; k0 += GBK) {
        // A tile: 128x16 = 512 float4, 2 per thread
        #pragma unroll
        for (int i = 0; i < 2; i++) {
            int idx = tid + i * 256;
            int r = idx >> 2, cc = (idx & 3) * 4;
            int gr = row0 + r;
            float4 v = make_float4(0.f, 0.f, 0.f, 0.f);
            if (gr < M) v = *(const float4*)(A + (size_t)gr * K + k0 + cc);
            float xs[4] = {v.x, v.y, v.z, v.w};
            #pragma unroll
            for (int j = 0; j < 4; j++) {
                unsigned hi = cvt_tf32(xs[j]);
                As_hi[r][cc + j] = hi;
                As_lo[r][cc + j] = cvt_tf32(xs[j] - __uint_as_float(hi));
            }
        }
        // B tile: 16x128 = 512 float4, 2 per thread
        #pragma unroll
        for (int i = 0; i < 2; i++) {
            int idx = tid + i * 256;
            int r = idx >> 5, cc = (idx & 31) * 4;
            float4 v = *(const float4*)(B + (size_t)(k0 + r) * N + col0 + cc);
            float xs[4] = {v.x, v.y, v.z, v.w};
            #pragma unroll
            for (int j = 0; j < 4; j++) {
                unsigned hi = cvt_tf32(xs[j]);
                Bs_hi[r][cc + j] = hi;
                Bs_lo[r][cc + j] = cvt_tf32(xs[j] - __uint_as_float(hi));
            }
        }
        __syncthreads();

        #pragma unroll
        for (int k8 = 0; k8 < GBK / 8; k8++) {
            unsigned ah[4][4], al[4][4], bh[4][2], bl[4][2];
            #pragma unroll
            for (int mt = 0; mt < 4; mt++) {
                int r = wm + mt * 16 + grp;
                int kc = k8 * 8 + tig;
                ah[mt][0] = As_hi[r][kc];         ah[mt][1] = As_hi[r + 8][kc];
                ah[mt][2] = As_hi[r][kc + 4];     ah[mt][3] = As_hi[r + 8][kc + 4];
                al[mt][0] = As_lo[r][kc];         al[mt][1] = As_lo[r + 8][kc];
                al[mt][2] = As_lo[r][kc + 4];     al[mt][3] = As_lo[r + 8][kc + 4];
            }
            #pragma unroll
            for (int nt = 0; nt < 4; nt++) {
                int cn = wn + nt * 8 + grp;
                bh[nt][0] = Bs_hi[k8 * 8 + tig][cn];
                bh[nt][1] = Bs_hi[k8 * 8 + tig + 4][cn];
                bl[nt][0] = Bs_lo[k8 * 8 + tig][cn];
                bl[nt][1] = Bs_lo[k8 * 8 + tig + 4][cn];
            }
            #pragma unroll
            for (int mt = 0; mt < 4; mt++)
                #pragma unroll
                for (int nt = 0; nt < 4; nt++) {
                    mma_tf32(c[mt][nt], ah[mt], bl[nt]);
                    mma_tf32(c[mt][nt], al[mt], bh[nt]);
                    mma_tf32(c[mt][nt], ah[mt], bh[nt]);
                }
        }
        __syncthreads();
    }

    // epilogue: bias add + store
    #pragma unroll
    for (int nt = 0; nt < 4; nt++) {
        int cc = col0 + wn + nt * 8 + 2 * tig;
        float b0 = bias[cc], b1 = bias[cc + 1];
        #pragma unroll
        for (int mt = 0; mt < 4; mt++) {
            int r0 = row0 + wm + mt * 16 + grp;
            if (r0 < M)
                *(float2*)(C + (size_t)r0 * N + cc) =
                    make_float2(c[mt][nt][0] + b0, c[mt][nt][1] + b1);
            if (r0 + 8 < M)
                *(float2*)(C + (size_t)(r0 + 8) * N + cc) =
                    make_float2(c[mt][nt][2] + b0, c[mt][nt][3] + b1);
        }
    }
}

// ---------------- CSR build (once per launch) --------------------------------
__global__ void zero_cnt_kernel() {
    int i = blockIdx.x * blockDim.x + threadIdx.x;
    if (i < NN) g_cnt[i] = 0;
}

__global__ void count_kernel(const int* __restrict__ dst) {
    int e = blockIdx.x * blockDim.x + threadIdx.x;
    if (e < NE) atomicAdd(&g_cnt[dst[e]], 1);
}

__global__ __launch_bounds__(1024) void scan_kernel() {
    __shared__ int s[1024];
    int t = threadIdx.x;
    int lo = t * 20;
    int hi = lo + 20; if (hi > NN) hi = NN;
    int sum = 0;
    for (int i = lo; i < hi; i++) sum += g_cnt[i];
    s[t] = sum;
    __syncthreads();
    for (int off = 1; off < 1024; off <<= 1) {
        int v = (t >= off) ? s[t - off] : 0;
        __syncthreads();
        s[t] += v;
        __syncthreads();
    }
    int run = s[t] - sum;   // exclusive prefix at chunk start
    for (int i = lo; i < hi; i++) {
        g_base[i] = run;
        g_cur[i] = run;
        run += g_cnt[i];
    }
    if (t == 0) g_base[NN] = NE;
}

__global__ void fill_kernel(const int* __restrict__ dst) {
    int e = blockIdx.x * blockDim.x + threadIdx.x;
    if (e < NE) {
        int p = atomicAdd(&g_cur[dst[e]], 1);
        g_ebyd[p] = e;
    }
}

// ---------------- edge scores (warp per edge, no atomics) --------------------
__global__ void edge_score_kernel(const int* __restrict__ src,
                                  const int* __restrict__ dst,
                                  const float* __restrict__ attn)
{
    int warp = (blockIdx.x * blockDim.x + threadIdx.x) >> 5;
    int lane = threadIdx.x & 31;
    if (warp >= NE) return;
    int s = src[warp];
    int d = dst[warp];
    const float* fsrow = g_fs + (size_t)s * HID;
    const float* fdrow = g_fd + (size_t)d * HID;
    #pragma unroll
    for (int h = 0; h < HEADS; h++) {
        float v = fsrow[h * DH + lane] + fdrow[h * DH + lane];
        v = (v > 0.f) ? v : SLOPE * v;
        float p = v * attn[h * DH + lane];
        #pragma unroll
        for (int o = 16; o; o >>= 1) p += __shfl_xor_sync(0xffffffffu, p, o);
        if (lane == 0) g_score[(size_t)warp * HEADS + h] = p;
    }
}

// ---------------- per-(node,head) softmax stats -------------------------------
__global__ void node_softmax_kernel() {
    int i = blockIdx.x * blockDim.x + threadIdx.x;
    if (i >= NN * HEADS) return;
    int n = i >> 3;
    int h = i & 7;
    int b = g_base[n], e2 = g_base[n + 1];
    float m = -1e30f;
    for (int j = b; j < e2; j++) {
        float v = g_score[(size_t)g_ebyd[j] * HEADS + h];
        m = fmaxf(m, v);
    }
    float s = 0.f;
    for (int j = b; j < e2; j++)
        s += expf(g_score[(size_t)g_ebyd[j] * HEADS + h] - m);
    g_m[i] = m;
    g_inv[i] = (s > 0.f) ? 1.f / s : 0.f;
}

// ---------------- gather: rst + residual + relu, no atomics ------------------
// warp per (node, head); lane = dim within head
__global__ void gather_kernel(const int* __restrict__ src) {
    int gid = blockIdx.x * (blockDim.x >> 5) + (threadIdx.x >> 5);
    int lane = threadIdx.x & 31;
    if (gid >= NN * HEADS) return;
    int n = gid >> 3;
    int h = gid & 7;
    float m = g_m[gid];
    float inv = g_inv[gid];
    int b = g_base[n], e2 = g_base[n + 1];
    float acc = 0.f;
    for (int j = b; j < e2; j++) {
        int e = g_ebyd[j];
        float alpha = expf(g_score[(size_t)e * HEADS + h] - m) * inv;
        acc = fmaf(alpha, g_fs[(size_t)src[e] * HID + h * DH + lane], acc);
    }
    size_t off = (size_t)n * HID + h * DH + lane;
    g_h[off] = fmaxf(acc + g_h[off], 0.f);
}

// ---------------- graph sum pooling -------------------------------------------
__global__ void zero_hg_kernel() {
    int i = blockIdx.x * blockDim.x + threadIdx.x;
    if (i < NG * HID) g_hg[i] = 0.f;
}

__global__ void pool_kernel(const int* __restrict__ graph_ids) {
    int i = blockIdx.x * blockDim.x + threadIdx.x;
    if (i >= NN * HID) return;
    int n = i >> 8;
    int ccol = i & 255;
    atomicAdd(&g_hg[graph_ids[n] * HID + ccol], g_h[i]);
}

// ---------------- small FC: Y = act(X@W + b) ----------------------------------
__global__ void fc_kernel(const float* __restrict__ X, const float* __restrict__ W,
                          const float* __restrict__ b, float* __restrict__ Y,
                          int N, int K, int do_relu)
{
    __shared__ float xs[256];
    int row = blockIdx.x;
    for (int i = threadIdx.x; i < K; i += blockDim.x) xs[i] = X[row * K + i];
    __syncthreads();
    int col = threadIdx.x;
    if (col < N) {
        float s = b[col];
        for (int k = 0; k < K; k++) s = fmaf(xs[k], W[k * N + col], s);
        if (do_relu) s = fmaxf(s, 0.f);
        Y[row * N + col] = s;
    }
}

// ---------------- launch -------------------------------------------------------
extern "C" void kernel_launch(void* const* d_in, const int* in_sizes, int n_in,
                              void* d_out, int out_size)
{
    const float* feature   = (const float*)d_in[0];
    const float* W_in      = (const float*)d_in[1];
    const float* b_in      = (const float*)d_in[2];
    const float* W_src     = (const float*)d_in[3];
    const float* b_src     = (const float*)d_in[4];
    const float* W_dst     = (const float*)d_in[5];
    const float* b_dst     = (const float*)d_in[6];
    const float* attn      = (const float*)d_in[7];
    const float* Wc1       = (const float*)d_in[8];
    const float* bc1       = (const float*)d_in[9];
    const float* Wc2       = (const float*)d_in[10];
    const float* bc2       = (const float*)d_in[11];
    const float* Wc3       = (const float*)d_in[12];
    const float* bc3       = (const float*)d_in[13];
    const int*   src       = (const int*)d_in[14];
    const int*   dst       = (const int*)d_in[15];
    const int*   graph_ids = (const int*)d_in[16];
    float* out = (float*)d_out;

    float *p_h, *p_fs, *p_fd, *p_hg, *p_x1, *p_x2;
    cudaGetSymbolAddress((void**)&p_h,  g_h);
    cudaGetSymbolAddress((void**)&p_fs, g_fs);
    cudaGetSymbolAddress((void**)&p_fd, g_fd);
    cudaGetSymbolAddress((void**)&p_hg, g_hg);
    cudaGetSymbolAddress((void**)&p_x1, g_x1);
    cudaGetSymbolAddress((void**)&p_x2, g_x2);

    // CSR by dst (identical every call; rebuilt deterministically up to edge order)
    zero_cnt_kernel<<<(NN + 255) / 256, 256>>>();
    count_kernel<<<(NE + 255) / 256, 256>>>(dst);
    scan_kernel<<<1, 1024>>>();
    fill_kernel<<<(NE + 255) / 256, 256>>>(dst);

    dim3 ggrid(HID / GBN, (NN + GBM - 1) / GBM);

    gemm_tf32_kernel<<<ggrid, 256>>>(feature, W_in, b_in, p_h, NN, HID, INDIM);

    const int escore_blocks = NE / 8;                 // warp per edge, 8 warps/block
    const int nsm_blocks = (NN * HEADS + 255) / 256;
    const int gather_blocks = NN * HEADS / 8;

    for (int l = 0; l < LAYERS; l++) {
        const float* Ws = W_src + (size_t)l * HID * HID;
        const float* bs = b_src + (size_t)l * HID;
        const float* Wd = W_dst + (size_t)l * HID * HID;
        const float* bd = b_dst + (size_t)l * HID;
        const float* al = attn + (size_t)l * HEADS * DH;

        gemm_tf32_kernel<<<ggrid, 256>>>(p_h, Ws, bs, p_fs, NN, HID, HID);
        gemm_tf32_kernel<<<ggrid, 256>>>(p_h, Wd, bd, p_fd, NN, HID, HID);
        edge_score_kernel<<<escore_blocks, 256>>>(src, dst, al);
        node_softmax_kernel<<<nsm_blocks, 256>>>();
        gather_kernel<<<gather_blocks, 256>>>(src);
    }

    zero_hg_kernel<<<(NG * HID + 255) / 256, 256>>>();
    pool_kernel<<<(NN * HID + 255) / 256, 256>>>(graph_ids);

    fc_kernel<<<NG, 256>>>(p_hg, Wc1, bc1, p_x1, HID, HID, 1);
    fc_kernel<<<NG, 256>>>(p_x1, Wc2, bc2, p_x2, HID / 2, HID, 1);
    fc_kernel<<<NG, 256>>>(p_x2, Wc3, bc3, out, OUTDIM, HID / 2, 0);
}

// round 3
// speedup vs baseline: 1.6967x; 1.3597x over previous
#include <cuda_runtime.h>
#include <cuda_bf16.h>
#include <math.h>

#define NN      20000
#define NE      320000
#define INDIM   128
#define HID     256
#define HEADS   8
#define DH      32
#define LAYERS  3
#define NG      64
#define OUTDIM  10
#define SLOPE   0.2f

// ---------------- scratch (device globals; no allocation allowed) ----------
__device__ float g_h[NN * HID];
__device__ float g_fs[NN * HID];
__device__ float g_fd[NN * HID];
__device__ float g_hg[NG * HID];
__device__ float g_x1[NG * HID];
__device__ float g_x2[NG * (HID / 2)];
// CSR by dst
__device__ int g_cnt[NN];
__device__ int g_base[NN + 1];
__device__ int g_cur[NN];
__device__ int g_srcbyd[NE];     // src node id, grouped by dst
__device__ int g_gstart[NG + 1]; // graph boundaries in sorted graph_ids

// ---------------- tf32 helpers ----------------------------------------------
__device__ __forceinline__ unsigned cvt_tf32(float x) {
    unsigned r;
    asm("cvt.rna.tf32.f32 %0, %1;" : "=r"(r) : "f"(x));
    return r;
}

__device__ __forceinline__ void mma_tf32(float c[4], const unsigned a[4], const unsigned b[2]) {
    asm volatile(
        "mma.sync.aligned.m16n8k8.row.col.f32.tf32.tf32.f32 "
        "{%0,%1,%2,%3}, {%4,%5,%6,%7}, {%8,%9}, {%0,%1,%2,%3};"
        : "+f"(c[0]), "+f"(c[1]), "+f"(c[2]), "+f"(c[3])
        : "r"(a[0]), "r"(a[1]), "r"(a[2]), "r"(a[3]), "r"(b[0]), "r"(b[1]));
}

// ---------------- tensor-core GEMM (3xTF32 split, fp32-accurate) ------------
// C[M,N] = A[M,K] @ B[K,N] + bias[N].  K%16==0, N%128==0.
#define GBM 128
#define GBN 128
#define GBK 16

__global__ __launch_bounds__(256) void gemm_tf32_kernel(
    const float* __restrict__ A, const float* __restrict__ B,
    const float* __restrict__ bias, float* __restrict__ C,
    int M, int N, int K)
{
    __shared__ unsigned As_hi[GBM][GBK + 4];
    __shared__ unsigned As_lo[GBM][GBK + 4];
    __shared__ unsigned Bs_hi[GBK][GBN + 8];
    __shared__ unsigned Bs_lo[GBK][GBN + 8];

    const int tid  = threadIdx.x;
    const int wid  = tid >> 5;
    const int lane = tid & 31;
    const int wm   = (wid >> 2) * 64;
    const int wn   = (wid & 3) * 32;
    const int grp  = lane >> 2;
    const int tig  = lane & 3;
    const int row0 = blockIdx.y * GBM;
    const int col0 = blockIdx.x * GBN;

    float c[4][4][4];
    #pragma unroll
    for (int i = 0; i < 4; i++)
        #pragma unroll
        for (int j = 0; j < 4; j++)
            #pragma unroll
            for (int k = 0; k < 4; k++) c[i][j][k] = 0.f;

    for (int k0 = 0; k0 < K; k0 += GBK) {
        #pragma unroll
        for (int i = 0; i < 2; i++) {
            int idx = tid + i * 256;
            int r = idx >> 2, cc = (idx & 3) * 4;
            int gr = row0 + r;
            float4 v = make_float4(0.f, 0.f, 0.f, 0.f);
            if (gr < M) v = *(const float4*)(A + (size_t)gr * K + k0 + cc);
            float xs[4] = {v.x, v.y, v.z, v.w};
            #pragma unroll
            for (int j = 0; j < 4; j++) {
                unsigned hi = cvt_tf32(xs[j]);
                As_hi[r][cc + j] = hi;
                As_lo[r][cc + j] = cvt_tf32(xs[j] - __uint_as_float(hi));
            }
        }
        #pragma unroll
        for (int i = 0; i < 2; i++) {
            int idx = tid + i * 256;
            int r = idx >> 5, cc = (idx & 31) * 4;
            float4 v = *(const float4*)(B + (size_t)(k0 + r) * N + col0 + cc);
            float xs[4] = {v.x, v.y, v.z, v.w};
            #pragma unroll
            for (int j = 0; j < 4; j++) {
                unsigned hi = cvt_tf32(xs[j]);
                Bs_hi[r][cc + j] = hi;
                Bs_lo[r][cc + j] = cvt_tf32(xs[j] - __uint_as_float(hi));
            }
        }
        __syncthreads();

        #pragma unroll
        for (int k8 = 0; k8 < GBK / 8; k8++) {
            unsigned ah[4][4], al[4][4], bh[4][2], bl[4][2];
            #pragma unroll
            for (int mt = 0; mt < 4; mt++) {
                int r = wm + mt * 16 + grp;
                int kc = k8 * 8 + tig;
                ah[mt][0] = As_hi[r][kc];         ah[mt][1] = As_hi[r + 8][kc];
                ah[mt][2] = As_hi[r][kc + 4];     ah[mt][3] = As_hi[r + 8][kc + 4];
                al[mt][0] = As_lo[r][kc];         al[mt][1] = As_lo[r + 8][kc];
                al[mt][2] = As_lo[r][kc + 4];     al[mt][3] = As_lo[r + 8][kc + 4];
            }
            #pragma unroll
            for (int nt = 0; nt < 4; nt++) {
                int cn = wn + nt * 8 + grp;
                bh[nt][0] = Bs_hi[k8 * 8 + tig][cn];
                bh[nt][1] = Bs_hi[k8 * 8 + tig + 4][cn];
                bl[nt][0] = Bs_lo[k8 * 8 + tig][cn];
                bl[nt][1] = Bs_lo[k8 * 8 + tig + 4][cn];
            }
            #pragma unroll
            for (int mt = 0; mt < 4; mt++)
                #pragma unroll
                for (int nt = 0; nt < 4; nt++) {
                    mma_tf32(c[mt][nt], ah[mt], bl[nt]);
                    mma_tf32(c[mt][nt], al[mt], bh[nt]);
                    mma_tf32(c[mt][nt], ah[mt], bh[nt]);
                }
        }
        __syncthreads();
    }

    #pragma unroll
    for (int nt = 0; nt < 4; nt++) {
        int cc = col0 + wn + nt * 8 + 2 * tig;
        float b0 = bias[cc], b1 = bias[cc + 1];
        #pragma unroll
        for (int mt = 0; mt < 4; mt++) {
            int r0 = row0 + wm + mt * 16 + grp;
            if (r0 < M)
                *(float2*)(C + (size_t)r0 * N + cc) =
                    make_float2(c[mt][nt][0] + b0, c[mt][nt][1] + b1);
            if (r0 + 8 < M)
                *(float2*)(C + (size_t)(r0 + 8) * N + cc) =
                    make_float2(c[mt][nt][2] + b0, c[mt][nt][3] + b1);
        }
    }
}

// ---------------- CSR build (once per launch) --------------------------------
__global__ void zero_cnt_kernel() {
    int i = blockIdx.x * blockDim.x + threadIdx.x;
    if (i < NN) g_cnt[i] = 0;
}

__global__ void count_kernel(const int* __restrict__ dst) {
    int e = blockIdx.x * blockDim.x + threadIdx.x;
    if (e < NE) atomicAdd(&g_cnt[dst[e]], 1);
}

__global__ __launch_bounds__(1024) void scan_kernel() {
    __shared__ int s[1024];
    int t = threadIdx.x;
    int lo = t * 20;
    int hi = lo + 20; if (hi > NN) hi = NN;
    int sum = 0;
    for (int i = lo; i < hi; i++) sum += g_cnt[i];
    s[t] = sum;
    __syncthreads();
    for (int off = 1; off < 1024; off <<= 1) {
        int v = (t >= off) ? s[t - off] : 0;
        __syncthreads();
        s[t] += v;
        __syncthreads();
    }
    int run = s[t] - sum;
    for (int i = lo; i < hi; i++) {
        g_base[i] = run;
        g_cur[i] = run;
        run += g_cnt[i];
    }
    if (t == 0) g_base[NN] = NE;
}

__global__ void fill_kernel(const int* __restrict__ src, const int* __restrict__ dst) {
    int e = blockIdx.x * blockDim.x + threadIdx.x;
    if (e < NE) {
        int p = atomicAdd(&g_cur[dst[e]], 1);
        g_srcbyd[p] = src[e];
    }
}

// ------- fused edge kernel: score + online softmax + aggregate + residual ----
// One warp per (node, head); lane = dim within head.
__global__ __launch_bounds__(256) void fused_edge_kernel(const float* __restrict__ attn)
{
    int gid = blockIdx.x * 8 + (threadIdx.x >> 5);
    int lane = threadIdx.x & 31;
    if (gid >= NN * HEADS) return;
    int n = gid >> 3;
    int h = gid & 7;

    const float fdv = g_fd[(size_t)n * HID + h * DH + lane];
    const float av  = attn[h * DH + lane];
    const int b  = g_base[n];
    const int e2 = g_base[n + 1];

    float m = -1e30f, sd = 0.f, acc = 0.f;
    for (int j = b; j < e2; j++) {
        int s = g_srcbyd[j];
        float fsv = g_fs[(size_t)s * HID + h * DH + lane];
        float v = fsv + fdv;
        v = (v > 0.f) ? v : SLOPE * v;
        float p = v * av;
        #pragma unroll
        for (int o = 16; o; o >>= 1) p += __shfl_xor_sync(0xffffffffu, p, o);
        float nm = fmaxf(m, p);
        float fac = __expf(m - nm);
        float w   = __expf(p - nm);
        sd  = sd * fac + w;
        acc = fmaf(acc, fac, w * fsv);
        m = nm;
    }
    float o = (sd > 0.f) ? acc / sd : 0.f;
    size_t off = (size_t)n * HID + h * DH + lane;
    g_h[off] = fmaxf(o + g_h[off], 0.f);
}

// ---------------- graph boundaries (graph_ids is sorted) ---------------------
__global__ void gbound_kernel(const int* __restrict__ gids) {
    int g = threadIdx.x;
    if (g > NG) return;
    int lo = 0, hi = NN;
    while (lo < hi) {
        int mid = (lo + hi) >> 1;
        if (gids[mid] < g) lo = mid + 1; else hi = mid;
    }
    g_gstart[g] = lo;
}

// ---------------- pooling: segmented sum, no atomics -------------------------
__global__ __launch_bounds__(256) void pool_kernel(void) {
    int g = blockIdx.x;
    int c = threadIdx.x;                 // 0..255
    int n0 = g_gstart[g], n1 = g_gstart[g + 1];
    float s = 0.f;
    int n = n0;
    for (; n + 4 <= n1; n += 4) {
        float a0 = g_h[(size_t)(n + 0) * HID + c];
        float a1 = g_h[(size_t)(n + 1) * HID + c];
        float a2 = g_h[(size_t)(n + 2) * HID + c];
        float a3 = g_h[(size_t)(n + 3) * HID + c];
        s += (a0 + a1) + (a2 + a3);
    }
    for (; n < n1; n++) s += g_h[(size_t)n * HID + c];
    g_hg[g * HID + c] = s;
}

// ---------------- small FC: Y = act(X@W + b) ----------------------------------
__global__ void fc_kernel(const float* __restrict__ X, const float* __restrict__ W,
                          const float* __restrict__ b, float* __restrict__ Y,
                          int N, int K, int do_relu)
{
    __shared__ float xs[256];
    int row = blockIdx.x;
    for (int i = threadIdx.x; i < K; i += blockDim.x) xs[i] = X[row * K + i];
    __syncthreads();
    int col = threadIdx.x;
    if (col < N) {
        float s = b[col];
        for (int k = 0; k < K; k++) s = fmaf(xs[k], W[k * N + col], s);
        if (do_relu) s = fmaxf(s, 0.f);
        Y[row * N + col] = s;
    }
}

// ---------------- launch -------------------------------------------------------
extern "C" void kernel_launch(void* const* d_in, const int* in_sizes, int n_in,
                              void* d_out, int out_size)
{
    const float* feature   = (const float*)d_in[0];
    const float* W_in      = (const float*)d_in[1];
    const float* b_in      = (const float*)d_in[2];
    const float* W_src     = (const float*)d_in[3];
    const float* b_src     = (const float*)d_in[4];
    const float* W_dst     = (const float*)d_in[5];
    const float* b_dst     = (const float*)d_in[6];
    const float* attn      = (const float*)d_in[7];
    const float* Wc1       = (const float*)d_in[8];
    const float* bc1       = (const float*)d_in[9];
    const float* Wc2       = (const float*)d_in[10];
    const float* bc2       = (const float*)d_in[11];
    const float* Wc3       = (const float*)d_in[12];
    const float* bc3       = (const float*)d_in[13];
    const int*   src       = (const int*)d_in[14];
    const int*   dst       = (const int*)d_in[15];
    const int*   graph_ids = (const int*)d_in[16];
    float* out = (float*)d_out;

    float *p_h, *p_fs, *p_fd, *p_hg, *p_x1, *p_x2;
    cudaGetSymbolAddress((void**)&p_h,  g_h);
    cudaGetSymbolAddress((void**)&p_fs, g_fs);
    cudaGetSymbolAddress((void**)&p_fd, g_fd);
    cudaGetSymbolAddress((void**)&p_hg, g_hg);
    cudaGetSymbolAddress((void**)&p_x1, g_x1);
    cudaGetSymbolAddress((void**)&p_x2, g_x2);

    // CSR by dst + graph boundaries
    zero_cnt_kernel<<<(NN + 255) / 256, 256>>>();
    count_kernel<<<(NE + 255) / 256, 256>>>(dst);
    scan_kernel<<<1, 1024>>>();
    fill_kernel<<<(NE + 255) / 256, 256>>>(src, dst);
    gbound_kernel<<<1, 128>>>(graph_ids);

    dim3 ggrid(HID / GBN, (NN + GBM - 1) / GBM);

    gemm_tf32_kernel<<<ggrid, 256>>>(feature, W_in, b_in, p_h, NN, HID, INDIM);

    const int fused_blocks = NN * HEADS / 8;   // warp per (node,head), 8 warps/block

    for (int l = 0; l < LAYERS; l++) {
        const float* Ws = W_src + (size_t)l * HID * HID;
        const float* bs = b_src + (size_t)l * HID;
        const float* Wd = W_dst + (size_t)l * HID * HID;
        const float* bd = b_dst + (size_t)l * HID;
        const float* al = attn + (size_t)l * HEADS * DH;

        gemm_tf32_kernel<<<ggrid, 256>>>(p_h, Ws, bs, p_fs, NN, HID, HID);
        gemm_tf32_kernel<<<ggrid, 256>>>(p_h, Wd, bd, p_fd, NN, HID, HID);
        fused_edge_kernel<<<fused_blocks, 256>>>(al);
    }

    pool_kernel<<<NG, 256>>>();

    fc_kernel<<<NG, 256>>>(p_hg, Wc1, bc1, p_x1, HID, HID, 1);
    fc_kernel<<<NG, 256>>>(p_x1, Wc2, bc2, p_x2, HID / 2, HID, 1);
    fc_kernel<<<NG, 256>>>(p_x2, Wc3, bc3, out, OUTDIM, HID / 2, 0);
}

// round 4
// speedup vs baseline: 2.1116x; 1.2445x over previous
#include <cuda_runtime.h>
#include <cuda_bf16.h>
#include <math.h>

#define NN      20000
#define NE      320000
#define INDIM   128
#define HID     256
#define HEADS   8
#define DH      32
#define LAYERS  3
#define NG      64
#define OUTDIM  10
#define SLOPE   0.2f

// ---------------- scratch (device globals; no allocation allowed) ----------
__device__ float g_h[NN * HID];
__device__ float g_fs[NN * HID];
__device__ float g_fd[NN * HID];
__device__ float g_hg[NG * HID];
__device__ float g_x1[NG * HID];
__device__ float g_x2[NG * (HID / 2)];
// packed bf16 pair buffers (hi/lo split)
__device__ unsigned g_ah_hi[NN * HID / 2];     // packed h   [NN][128]
__device__ unsigned g_ah_lo[NN * HID / 2];
__device__ unsigned g_af_hi[NN * INDIM / 2];   // packed feature [NN][64]
__device__ unsigned g_af_lo[NN * INDIM / 2];
__device__ unsigned g_win_hi[(INDIM / 2) * HID], g_win_lo[(INDIM / 2) * HID];
__device__ unsigned g_ws_hi[LAYERS * (HID / 2) * HID], g_ws_lo[LAYERS * (HID / 2) * HID];
__device__ unsigned g_wd_hi[LAYERS * (HID / 2) * HID], g_wd_lo[LAYERS * (HID / 2) * HID];
// CSR by dst
__device__ int g_cnt[NN];
__device__ int g_base[NN + 1];
__device__ int g_cur[NN];
__device__ int g_srcbyd[NE];
__device__ int g_gstart[NG + 1];

// ---------------- bf16 pack helpers -----------------------------------------
__device__ __forceinline__ unsigned pack_bf2(__nv_bfloat16 a, __nv_bfloat16 b) {
    return ((unsigned)__bfloat16_as_ushort(b) << 16) | (unsigned)__bfloat16_as_ushort(a);
}

__device__ __forceinline__ void split_pack(float x0, float x1, unsigned& hi, unsigned& lo) {
    __nv_bfloat16 h0 = __float2bfloat16_rn(x0);
    __nv_bfloat16 h1 = __float2bfloat16_rn(x1);
    __nv_bfloat16 l0 = __float2bfloat16_rn(x0 - __bfloat162float(h0));
    __nv_bfloat16 l1 = __float2bfloat16_rn(x1 - __bfloat162float(h1));
    hi = pack_bf2(h0, h1);
    lo = pack_bf2(l0, l1);
}

__device__ __forceinline__ void mma_bf16(float c[4], const unsigned a[4], const unsigned b[2]) {
    asm volatile(
        "mma.sync.aligned.m16n8k16.row.col.f32.bf16.bf16.f32 "
        "{%0,%1,%2,%3}, {%4,%5,%6,%7}, {%8,%9}, {%0,%1,%2,%3};"
        : "+f"(c[0]), "+f"(c[1]), "+f"(c[2]), "+f"(c[3])
        : "r"(a[0]), "r"(a[1]), "r"(a[2]), "r"(a[3]), "r"(b[0]), "r"(b[1]));
}

// ---------------- pack kernels ------------------------------------------------
// pack row-major float matrix into k-paired bf16 hi/lo (pairs along contiguous dim)
__global__ void pack_rows_kernel(const float* __restrict__ X,
                                 unsigned* __restrict__ hi, unsigned* __restrict__ lo,
                                 int npairs)
{
    int i = blockIdx.x * blockDim.x + threadIdx.x;
    if (i >= npairs) return;
    float2 v = ((const float2*)X)[i];
    split_pack(v.x, v.y, hi[i], lo[i]);
}

// pack weight W[K][N] into Wp[k2][n] (pairs along K, row length N)
__global__ void pack_w_kernel(const float* __restrict__ W,
                              unsigned* __restrict__ hi, unsigned* __restrict__ lo,
                              int K2, int N)
{
    int i = blockIdx.x * blockDim.x + threadIdx.x;
    if (i >= K2 * N) return;
    int k2 = i / N, n = i - k2 * N;
    float x0 = W[(2 * k2) * N + n];
    float x1 = W[(2 * k2 + 1) * N + n];
    split_pack(x0, x1, hi[i], lo[i]);
}

// ---------------- bf16x3 tensor-core GEMM ------------------------------------
// C[M,N] = A[M,K] @ B[K,N] + bias.  A/B pre-packed as bf16 hi/lo k-pairs.
// grid.x = nb (single) or 2*nb (dual output: B1->C1, B2->C2). nb = N/128.
#define GBM 128
#define GBN 128
#define AST 12
#define BST 136

__global__ __launch_bounds__(256) void gemm_bf16x3_kernel(
    const unsigned* __restrict__ Ahi, const unsigned* __restrict__ Alo,
    const unsigned* __restrict__ B1hi, const unsigned* __restrict__ B1lo,
    const unsigned* __restrict__ B2hi, const unsigned* __restrict__ B2lo,
    const float* __restrict__ bias1, const float* __restrict__ bias2,
    float* __restrict__ C1, float* __restrict__ C2,
    unsigned* __restrict__ Pho, unsigned* __restrict__ Plo,   // optional packed out
    int M, int N, int K2, int nb, int do_pack)
{
    __shared__ unsigned As_hi[GBM][AST];
    __shared__ unsigned As_lo[GBM][AST];
    __shared__ unsigned Bs_hi[8][BST];
    __shared__ unsigned Bs_lo[8][BST];

    int bx = blockIdx.x;
    int which = 0;
    if (bx >= nb) { which = 1; bx -= nb; }
    const unsigned* Bhi = which ? B2hi : B1hi;
    const unsigned* Blo = which ? B2lo : B1lo;
    const float* bias   = which ? bias2 : bias1;
    float* C            = which ? C2 : C1;

    const int tid  = threadIdx.x;
    const int wid  = tid >> 5;
    const int lane = tid & 31;
    const int wm   = (wid >> 2) * 64;
    const int wn   = (wid & 3) * 32;
    const int grp  = lane >> 2;
    const int tig  = lane & 3;
    const int row0 = blockIdx.y * GBM;
    const int col0 = bx * GBN;

    // tile-load thread mapping
    const int ar = tid >> 1;               // A row 0..127
    const int ac = (tid & 1) * 4;          // A pair-col 0 or 4
    const int brr = tid >> 5;              // B pair-row 0..7
    const int bcc = (tid & 31) * 4;        // B col 0..124

    const bool a_ok = (row0 + ar) < M;
    const size_t a_off = (size_t)(row0 + ar) * K2 + ac;

    float c[4][4][4];
    #pragma unroll
    for (int i = 0; i < 4; i++)
        #pragma unroll
        for (int j = 0; j < 4; j++)
            #pragma unroll
            for (int k = 0; k < 4; k++) c[i][j][k] = 0.f;

    uint4 vah = make_uint4(0,0,0,0), val_ = vah, vbh, vbl;

    // prefetch tile 0
    if (a_ok) {
        vah = *(const uint4*)(Ahi + a_off);
        val_ = *(const uint4*)(Alo + a_off);
    }
    vbh = *(const uint4*)(Bhi + (size_t)brr * N + col0 + bcc);
    vbl = *(const uint4*)(Blo + (size_t)brr * N + col0 + bcc);
    *(uint4*)&As_hi[ar][ac] = vah;
    *(uint4*)&As_lo[ar][ac] = val_;
    *(uint4*)&Bs_hi[brr][bcc] = vbh;
    *(uint4*)&Bs_lo[brr][bcc] = vbl;
    __syncthreads();

    const int nk = K2 >> 3;   // tiles of 8 pairs (16 k)
    for (int t = 0; t < nk; t++) {
        if (t + 1 < nk) {
            int kp = (t + 1) * 8;
            if (a_ok) {
                vah = *(const uint4*)(Ahi + a_off + kp);
                val_ = *(const uint4*)(Alo + a_off + kp);
            }
            vbh = *(const uint4*)(Bhi + (size_t)(kp + brr) * N + col0 + bcc);
            vbl = *(const uint4*)(Blo + (size_t)(kp + brr) * N + col0 + bcc);
        }

        unsigned ah[4][4], al[4][4], bh[4][2], bl[4][2];
        #pragma unroll
        for (int mt = 0; mt < 4; mt++) {
            int r = wm + mt * 16 + grp;
            ah[mt][0] = As_hi[r][tig];      ah[mt][1] = As_hi[r + 8][tig];
            ah[mt][2] = As_hi[r][tig + 4];  ah[mt][3] = As_hi[r + 8][tig + 4];
            al[mt][0] = As_lo[r][tig];      al[mt][1] = As_lo[r + 8][tig];
            al[mt][2] = As_lo[r][tig + 4];  al[mt][3] = As_lo[r + 8][tig + 4];
        }
        #pragma unroll
        for (int nt = 0; nt < 4; nt++) {
            int cn = wn + nt * 8 + grp;
            bh[nt][0] = Bs_hi[tig][cn];     bh[nt][1] = Bs_hi[tig + 4][cn];
            bl[nt][0] = Bs_lo[tig][cn];     bl[nt][1] = Bs_lo[tig + 4][cn];
        }
        #pragma unroll
        for (int mt = 0; mt < 4; mt++)
            #pragma unroll
            for (int nt = 0; nt < 4; nt++) {
                mma_bf16(c[mt][nt], ah[mt], bl[nt]);
                mma_bf16(c[mt][nt], al[mt], bh[nt]);
                mma_bf16(c[mt][nt], ah[mt], bh[nt]);
            }
        __syncthreads();
        if (t + 1 < nk) {
            *(uint4*)&As_hi[ar][ac] = vah;
            *(uint4*)&As_lo[ar][ac] = val_;
            *(uint4*)&Bs_hi[brr][bcc] = vbh;
            *(uint4*)&Bs_lo[brr][bcc] = vbl;
            __syncthreads();
        }
    }

    // epilogue: bias, store float2, optional packed bf16 pair output
    #pragma unroll
    for (int nt = 0; nt < 4; nt++) {
        int cc = col0 + wn + nt * 8 + 2 * tig;
        float b0 = bias[cc], b1 = bias[cc + 1];
        #pragma unroll
        for (int mt = 0; mt < 4; mt++) {
            int r0 = row0 + wm + mt * 16 + grp;
            if (r0 < M) {
                float v0 = c[mt][nt][0] + b0, v1 = c[mt][nt][1] + b1;
                *(float2*)(C + (size_t)r0 * N + cc) = make_float2(v0, v1);
                if (do_pack && which == 0) {
                    unsigned hi, lo;
                    split_pack(v0, v1, hi, lo);
                    size_t pi = ((size_t)r0 * N + cc) >> 1;
                    Pho[pi] = hi; Plo[pi] = lo;
                }
            }
            int r1 = r0 + 8;
            if (r1 < M) {
                float v0 = c[mt][nt][2] + b0, v1 = c[mt][nt][3] + b1;
                *(float2*)(C + (size_t)r1 * N + cc) = make_float2(v0, v1);
                if (do_pack && which == 0) {
                    unsigned hi, lo;
                    split_pack(v0, v1, hi, lo);
                    size_t pi = ((size_t)r1 * N + cc) >> 1;
                    Pho[pi] = hi; Plo[pi] = lo;
                }
            }
        }
    }
}

// ---------------- CSR build (once per launch) --------------------------------
__global__ void zero_cnt_kernel() {
    int i = blockIdx.x * blockDim.x + threadIdx.x;
    if (i < NN) g_cnt[i] = 0;
}

__global__ void count_kernel(const int* __restrict__ dst) {
    int e = blockIdx.x * blockDim.x + threadIdx.x;
    if (e < NE) atomicAdd(&g_cnt[dst[e]], 1);
}

__global__ __launch_bounds__(1024) void scan_kernel() {
    __shared__ int s[1024];
    int t = threadIdx.x;
    int lo = t * 20;
    int hi = lo + 20; if (hi > NN) hi = NN;
    int sum = 0;
    for (int i = lo; i < hi; i++) sum += g_cnt[i];
    s[t] = sum;
    __syncthreads();
    for (int off = 1; off < 1024; off <<= 1) {
        int v = (t >= off) ? s[t - off] : 0;
        __syncthreads();
        s[t] += v;
        __syncthreads();
    }
    int run = s[t] - sum;
    for (int i = lo; i < hi; i++) {
        g_base[i] = run;
        g_cur[i] = run;
        run += g_cnt[i];
    }
    if (t == 0) g_base[NN] = NE;
}

__global__ void fill_kernel(const int* __restrict__ src, const int* __restrict__ dst) {
    int e = blockIdx.x * blockDim.x + threadIdx.x;
    if (e < NE) {
        int p = atomicAdd(&g_cur[dst[e]], 1);
        g_srcbyd[p] = src[e];
    }
}

// ------- fused edge kernel: score + online softmax + aggregate + residual ----
// One warp per (node, head); also emits packed bf16 h for the next GEMM.
__global__ __launch_bounds__(256) void fused_edge_kernel(const float* __restrict__ attn)
{
    int gid = blockIdx.x * 8 + (threadIdx.x >> 5);
    int lane = threadIdx.x & 31;
    if (gid >= NN * HEADS) return;
    int n = gid >> 3;
    int h = gid & 7;

    const float fdv = g_fd[(size_t)n * HID + h * DH + lane];
    const float av  = attn[h * DH + lane];
    const int b  = g_base[n];
    const int e2 = g_base[n + 1];

    float m = -1e30f, sd = 0.f, acc = 0.f;
    for (int j = b; j < e2; j++) {
        int s = g_srcbyd[j];
        float fsv = g_fs[(size_t)s * HID + h * DH + lane];
        float v = fsv + fdv;
        v = (v > 0.f) ? v : SLOPE * v;
        float p = v * av;
        #pragma unroll
        for (int o = 16; o; o >>= 1) p += __shfl_xor_sync(0xffffffffu, p, o);
        float nm = fmaxf(m, p);
        float fac = __expf(m - nm);
        float w   = __expf(p - nm);
        sd  = sd * fac + w;
        acc = fmaf(acc, fac, w * fsv);
        m = nm;
    }
    float o = (sd > 0.f) ? acc / sd : 0.f;
    size_t off = (size_t)n * HID + h * DH + lane;
    float hv = fmaxf(o + g_h[off], 0.f);
    g_h[off] = hv;
    // pack pairs for next GEMM
    float other = __shfl_xor_sync(0xffffffffu, hv, 1);
    if ((lane & 1) == 0) {
        unsigned hi, lo;
        split_pack(hv, other, hi, lo);
        g_ah_hi[off >> 1] = hi;
        g_ah_lo[off >> 1] = lo;
    }
}

// ---------------- graph boundaries (graph_ids is sorted) ---------------------
__global__ void gbound_kernel(const int* __restrict__ gids) {
    int g = threadIdx.x;
    if (g > NG) return;
    int lo = 0, hi = NN;
    while (lo < hi) {
        int mid = (lo + hi) >> 1;
        if (gids[mid] < g) lo = mid + 1; else hi = mid;
    }
    g_gstart[g] = lo;
}

// ---------------- pooling: segmented sum, no atomics -------------------------
__global__ __launch_bounds__(256) void pool_kernel(void) {
    int g = blockIdx.x;
    int c = threadIdx.x;
    int n0 = g_gstart[g], n1 = g_gstart[g + 1];
    float s = 0.f;
    int n = n0;
    for (; n + 4 <= n1; n += 4) {
        float a0 = g_h[(size_t)(n + 0) * HID + c];
        float a1 = g_h[(size_t)(n + 1) * HID + c];
        float a2 = g_h[(size_t)(n + 2) * HID + c];
        float a3 = g_h[(size_t)(n + 3) * HID + c];
        s += (a0 + a1) + (a2 + a3);
    }
    for (; n < n1; n++) s += g_h[(size_t)n * HID + c];
    g_hg[g * HID + c] = s;
}

// ---------------- small FC -----------------------------------------------------
__global__ void fc_kernel(const float* __restrict__ X, const float* __restrict__ W,
                          const float* __restrict__ b, float* __restrict__ Y,
                          int N, int K, int do_relu)
{
    __shared__ float xs[256];
    int row = blockIdx.x;
    for (int i = threadIdx.x; i < K; i += blockDim.x) xs[i] = X[row * K + i];
    __syncthreads();
    int col = threadIdx.x;
    if (col < N) {
        float s = b[col];
        for (int k = 0; k < K; k++) s = fmaf(xs[k], W[k * N + col], s);
        if (do_relu) s = fmaxf(s, 0.f);
        Y[row * N + col] = s;
    }
}

// ---------------- launch -------------------------------------------------------
extern "C" void kernel_launch(void* const* d_in, const int* in_sizes, int n_in,
                              void* d_out, int out_size)
{
    const float* feature   = (const float*)d_in[0];
    const float* W_in      = (const float*)d_in[1];
    const float* b_in      = (const float*)d_in[2];
    const float* W_src     = (const float*)d_in[3];
    const float* b_src     = (const float*)d_in[4];
    const float* W_dst     = (const float*)d_in[5];
    const float* b_dst     = (const float*)d_in[6];
    const float* attn      = (const float*)d_in[7];
    const float* Wc1       = (const float*)d_in[8];
    const float* bc1       = (const float*)d_in[9];
    const float* Wc2       = (const float*)d_in[10];
    const float* bc2       = (const float*)d_in[11];
    const float* Wc3       = (const float*)d_in[12];
    const float* bc3       = (const float*)d_in[13];
    const int*   src       = (const int*)d_in[14];
    const int*   dst       = (const int*)d_in[15];
    const int*   graph_ids = (const int*)d_in[16];
    float* out = (float*)d_out;

    float *p_h, *p_fs, *p_fd, *p_hg, *p_x1, *p_x2;
    unsigned *p_ah_hi, *p_ah_lo, *p_af_hi, *p_af_lo;
    unsigned *p_win_hi, *p_win_lo, *p_ws_hi, *p_ws_lo, *p_wd_hi, *p_wd_lo;
    cudaGetSymbolAddress((void**)&p_h,  g_h);
    cudaGetSymbolAddress((void**)&p_fs, g_fs);
    cudaGetSymbolAddress((void**)&p_fd, g_fd);
    cudaGetSymbolAddress((void**)&p_hg, g_hg);
    cudaGetSymbolAddress((void**)&p_x1, g_x1);
    cudaGetSymbolAddress((void**)&p_x2, g_x2);
    cudaGetSymbolAddress((void**)&p_ah_hi, g_ah_hi);
    cudaGetSymbolAddress((void**)&p_ah_lo, g_ah_lo);
    cudaGetSymbolAddress((void**)&p_af_hi, g_af_hi);
    cudaGetSymbolAddress((void**)&p_af_lo, g_af_lo);
    cudaGetSymbolAddress((void**)&p_win_hi, g_win_hi);
    cudaGetSymbolAddress((void**)&p_win_lo, g_win_lo);
    cudaGetSymbolAddress((void**)&p_ws_hi, g_ws_hi);
    cudaGetSymbolAddress((void**)&p_ws_lo, g_ws_lo);
    cudaGetSymbolAddress((void**)&p_wd_hi, g_wd_hi);
    cudaGetSymbolAddress((void**)&p_wd_lo, g_wd_lo);

    // CSR by dst + graph boundaries
    zero_cnt_kernel<<<(NN + 255) / 256, 256>>>();
    count_kernel<<<(NE + 255) / 256, 256>>>(dst);
    scan_kernel<<<1, 1024>>>();
    fill_kernel<<<(NE + 255) / 256, 256>>>(src, dst);
    gbound_kernel<<<1, 128>>>(graph_ids);

    // pack weights
    const int WIN_P = (INDIM / 2) * HID;   // 16384
    const int WL_P  = (HID / 2) * HID;     // 32768
    pack_w_kernel<<<(WIN_P + 255) / 256, 256>>>(W_in, p_win_hi, p_win_lo, INDIM / 2, HID);
    for (int l = 0; l < LAYERS; l++) {
        pack_w_kernel<<<(WL_P + 255) / 256, 256>>>(W_src + (size_t)l * HID * HID,
            p_ws_hi + (size_t)l * WL_P, p_ws_lo + (size_t)l * WL_P, HID / 2, HID);
        pack_w_kernel<<<(WL_P + 255) / 256, 256>>>(W_dst + (size_t)l * HID * HID,
            p_wd_hi + (size_t)l * WL_P, p_wd_lo + (size_t)l * WL_P, HID / 2, HID);
    }
    // pack feature
    pack_rows_kernel<<<(NN * INDIM / 2 + 255) / 256, 256>>>(feature, p_af_hi, p_af_lo, NN * INDIM / 2);

    const int MROWS = (NN + GBM - 1) / GBM;   // 157
    dim3 grid1(HID / GBN, MROWS);             // (2,157)
    dim3 grid2(2 * (HID / GBN), MROWS);       // (4,157)

    // h = feature @ W_in + b_in   (also emit packed h)
    gemm_bf16x3_kernel<<<grid1, 256>>>(
        p_af_hi, p_af_lo, p_win_hi, p_win_lo, p_win_hi, p_win_lo,
        b_in, b_in, p_h, p_h, p_ah_hi, p_ah_lo,
        NN, HID, INDIM / 2, HID / GBN, 1);

    const int fused_blocks = NN * HEADS / 8;

    for (int l = 0; l < LAYERS; l++) {
        const float* bs = b_src + (size_t)l * HID;
        const float* bd = b_dst + (size_t)l * HID;
        const float* al = attn + (size_t)l * HEADS * DH;

        gemm_bf16x3_kernel<<<grid2, 256>>>(
            p_ah_hi, p_ah_lo,
            p_ws_hi + (size_t)l * WL_P, p_ws_lo + (size_t)l * WL_P,
            p_wd_hi + (size_t)l * WL_P, p_wd_lo + (size_t)l * WL_P,
            bs, bd, p_fs, p_fd, (unsigned*)0, (unsigned*)0,
            NN, HID, HID / 2, HID / GBN, 0);

        fused_edge_kernel<<<fused_blocks, 256>>>(al);
    }

    pool_kernel<<<NG, 256>>>();

    fc_kernel<<<NG, 256>>>(p_hg, Wc1, bc1, p_x1, HID, HID, 1);
    fc_kernel<<<NG, 256>>>(p_x1, Wc2, bc2, p_x2, HID / 2, HID, 1);
    fc_kernel<<<NG, 256>>>(p_x2, Wc3, bc3, out, OUTDIM, HID / 2, 0);
}

// round 5
// speedup vs baseline: 3.2307x; 1.5300x over previous
#include <cuda_runtime.h>
#include <cuda_bf16.h>
#include <math.h>

#define NN      20000
#define NE      320000
#define INDIM   128
#define HID     256
#define HEADS   8
#define DH      32
#define LAYERS  3
#define NG      64
#define OUTDIM  10
#define SLOPE   0.2f

// ---------------- scratch (device globals; no allocation allowed) ----------
__device__ float g_h[NN * HID];
__device__ float g_fs[NN * HID];
__device__ float g_fd[NN * HID];
__device__ float g_hg[NG * HID];
__device__ float g_x1[NG * HID];
__device__ float g_x2[NG * (HID / 2)];
// packed bf16 pair buffers (hi/lo split)
__device__ unsigned g_ah_hi[NN * HID / 2];
__device__ unsigned g_ah_lo[NN * HID / 2];
__device__ unsigned g_af_hi[NN * INDIM / 2];
__device__ unsigned g_af_lo[NN * INDIM / 2];
__device__ unsigned g_win_hi[(INDIM / 2) * HID], g_win_lo[(INDIM / 2) * HID];
__device__ unsigned g_ws_hi[LAYERS * (HID / 2) * HID], g_ws_lo[LAYERS * (HID / 2) * HID];
__device__ unsigned g_wd_hi[LAYERS * (HID / 2) * HID], g_wd_lo[LAYERS * (HID / 2) * HID];
// CSR by dst
__device__ int g_cnt[NN];
__device__ int g_base[NN + 1];
__device__ int g_cur[NN];
__device__ int g_srcbyd[NE];
__device__ int g_gstart[NG + 1];

// ---------------- bf16 pack helpers -----------------------------------------
__device__ __forceinline__ unsigned pack_bf2(__nv_bfloat16 a, __nv_bfloat16 b) {
    return ((unsigned)__bfloat16_as_ushort(b) << 16) | (unsigned)__bfloat16_as_ushort(a);
}

__device__ __forceinline__ void split_pack(float x0, float x1, unsigned& hi, unsigned& lo) {
    __nv_bfloat16 h0 = __float2bfloat16_rn(x0);
    __nv_bfloat16 h1 = __float2bfloat16_rn(x1);
    __nv_bfloat16 l0 = __float2bfloat16_rn(x0 - __bfloat162float(h0));
    __nv_bfloat16 l1 = __float2bfloat16_rn(x1 - __bfloat162float(h1));
    hi = pack_bf2(h0, h1);
    lo = pack_bf2(l0, l1);
}

__device__ __forceinline__ void mma_bf16(float c[4], const unsigned a[4], const unsigned b[2]) {
    asm volatile(
        "mma.sync.aligned.m16n8k16.row.col.f32.bf16.bf16.f32 "
        "{%0,%1,%2,%3}, {%4,%5,%6,%7}, {%8,%9}, {%0,%1,%2,%3};"
        : "+f"(c[0]), "+f"(c[1]), "+f"(c[2]), "+f"(c[3])
        : "r"(a[0]), "r"(a[1]), "r"(a[2]), "r"(a[3]), "r"(b[0]), "r"(b[1]));
}

// ---------------- pack kernels ------------------------------------------------
__global__ void pack_rows_kernel(const float* __restrict__ X,
                                 unsigned* __restrict__ hi, unsigned* __restrict__ lo,
                                 int npairs)
{
    int i = blockIdx.x * blockDim.x + threadIdx.x;
    if (i >= npairs) return;
    float2 v = ((const float2*)X)[i];
    split_pack(v.x, v.y, hi[i], lo[i]);
}

__global__ void pack_w_kernel(const float* __restrict__ W,
                              unsigned* __restrict__ hi, unsigned* __restrict__ lo,
                              int K2, int N)
{
    int i = blockIdx.x * blockDim.x + threadIdx.x;
    if (i >= K2 * N) return;
    int k2 = i / N, n = i - k2 * N;
    float x0 = W[(2 * k2) * N + n];
    float x1 = W[(2 * k2 + 1) * N + n];
    split_pack(x0, x1, hi[i], lo[i]);
}

// ---------------- bf16x3 tensor-core GEMM (double-buffered) ------------------
#define GBM 128
#define GBN 128
#define AST 12
#define BST 136

__global__ __launch_bounds__(256) void gemm_bf16x3_kernel(
    const unsigned* __restrict__ Ahi, const unsigned* __restrict__ Alo,
    const unsigned* __restrict__ B1hi, const unsigned* __restrict__ B1lo,
    const unsigned* __restrict__ B2hi, const unsigned* __restrict__ B2lo,
    const float* __restrict__ bias1, const float* __restrict__ bias2,
    float* __restrict__ C1, float* __restrict__ C2,
    unsigned* __restrict__ Pho, unsigned* __restrict__ Plo,
    int M, int N, int K2, int nb, int do_pack)
{
    __shared__ unsigned As_hi[2][GBM][AST];
    __shared__ unsigned As_lo[2][GBM][AST];
    __shared__ unsigned Bs_hi[2][8][BST];
    __shared__ unsigned Bs_lo[2][8][BST];

    int bx = blockIdx.x;
    int which = 0;
    if (bx >= nb) { which = 1; bx -= nb; }
    const unsigned* Bhi = which ? B2hi : B1hi;
    const unsigned* Blo = which ? B2lo : B1lo;
    const float* bias   = which ? bias2 : bias1;
    float* C            = which ? C2 : C1;

    const int tid  = threadIdx.x;
    const int wid  = tid >> 5;
    const int lane = tid & 31;
    const int wm   = (wid >> 2) * 64;
    const int wn   = (wid & 3) * 32;
    const int grp  = lane >> 2;
    const int tig  = lane & 3;
    const int row0 = blockIdx.y * GBM;
    const int col0 = bx * GBN;

    const int ar = tid >> 1;
    const int ac = (tid & 1) * 4;
    const int brr = tid >> 5;
    const int bcc = (tid & 31) * 4;

    const bool a_ok = (row0 + ar) < M;
    const size_t a_off = (size_t)(row0 + ar) * K2 + ac;

    float c[4][4][4];
    #pragma unroll
    for (int i = 0; i < 4; i++)
        #pragma unroll
        for (int j = 0; j < 4; j++)
            #pragma unroll
            for (int k = 0; k < 4; k++) c[i][j][k] = 0.f;

    uint4 vah = make_uint4(0,0,0,0), val_ = vah, vbh, vbl;

    // load tile 0 into buffer 0
    if (a_ok) {
        vah = *(const uint4*)(Ahi + a_off);
        val_ = *(const uint4*)(Alo + a_off);
    }
    vbh = *(const uint4*)(Bhi + (size_t)brr * N + col0 + bcc);
    vbl = *(const uint4*)(Blo + (size_t)brr * N + col0 + bcc);
    *(uint4*)&As_hi[0][ar][ac] = vah;
    *(uint4*)&As_lo[0][ar][ac] = val_;
    *(uint4*)&Bs_hi[0][brr][bcc] = vbh;
    *(uint4*)&Bs_lo[0][brr][bcc] = vbl;
    __syncthreads();

    const int nk = K2 >> 3;
    for (int t = 0; t < nk; t++) {
        const int cb = t & 1;
        const bool more = (t + 1 < nk);
        if (more) {
            int kp = (t + 1) * 8;
            if (a_ok) {
                vah = *(const uint4*)(Ahi + a_off + kp);
                val_ = *(const uint4*)(Alo + a_off + kp);
            }
            vbh = *(const uint4*)(Bhi + (size_t)(kp + brr) * N + col0 + bcc);
            vbl = *(const uint4*)(Blo + (size_t)(kp + brr) * N + col0 + bcc);
        }

        unsigned ah[4][4], al[4][4], bh[4][2], bl[4][2];
        #pragma unroll
        for (int mt = 0; mt < 4; mt++) {
            int r = wm + mt * 16 + grp;
            ah[mt][0] = As_hi[cb][r][tig];      ah[mt][1] = As_hi[cb][r + 8][tig];
            ah[mt][2] = As_hi[cb][r][tig + 4];  ah[mt][3] = As_hi[cb][r + 8][tig + 4];
            al[mt][0] = As_lo[cb][r][tig];      al[mt][1] = As_lo[cb][r + 8][tig];
            al[mt][2] = As_lo[cb][r][tig + 4];  al[mt][3] = As_lo[cb][r + 8][tig + 4];
        }
        #pragma unroll
        for (int nt = 0; nt < 4; nt++) {
            int cn = wn + nt * 8 + grp;
            bh[nt][0] = Bs_hi[cb][tig][cn];     bh[nt][1] = Bs_hi[cb][tig + 4][cn];
            bl[nt][0] = Bs_lo[cb][tig][cn];     bl[nt][1] = Bs_lo[cb][tig + 4][cn];
        }
        #pragma unroll
        for (int mt = 0; mt < 4; mt++)
            #pragma unroll
            for (int nt = 0; nt < 4; nt++) {
                mma_bf16(c[mt][nt], ah[mt], bl[nt]);
                mma_bf16(c[mt][nt], al[mt], bh[nt]);
                mma_bf16(c[mt][nt], ah[mt], bh[nt]);
            }

        if (more) {
            *(uint4*)&As_hi[1 - cb][ar][ac] = vah;
            *(uint4*)&As_lo[1 - cb][ar][ac] = val_;
            *(uint4*)&Bs_hi[1 - cb][brr][bcc] = vbh;
            *(uint4*)&Bs_lo[1 - cb][brr][bcc] = vbl;
            __syncthreads();
        }
    }

    #pragma unroll
    for (int nt = 0; nt < 4; nt++) {
        int cc = col0 + wn + nt * 8 + 2 * tig;
        float b0 = bias[cc], b1 = bias[cc + 1];
        #pragma unroll
        for (int mt = 0; mt < 4; mt++) {
            int r0 = row0 + wm + mt * 16 + grp;
            if (r0 < M) {
                float v0 = c[mt][nt][0] + b0, v1 = c[mt][nt][1] + b1;
                *(float2*)(C + (size_t)r0 * N + cc) = make_float2(v0, v1);
                if (do_pack && which == 0) {
                    unsigned hi, lo;
                    split_pack(v0, v1, hi, lo);
                    size_t pi = ((size_t)r0 * N + cc) >> 1;
                    Pho[pi] = hi; Plo[pi] = lo;
                }
            }
            int r1 = r0 + 8;
            if (r1 < M) {
                float v0 = c[mt][nt][2] + b0, v1 = c[mt][nt][3] + b1;
                *(float2*)(C + (size_t)r1 * N + cc) = make_float2(v0, v1);
                if (do_pack && which == 0) {
                    unsigned hi, lo;
                    split_pack(v0, v1, hi, lo);
                    size_t pi = ((size_t)r1 * N + cc) >> 1;
                    Pho[pi] = hi; Plo[pi] = lo;
                }
            }
        }
    }
}

// ---------------- CSR build (once per launch) --------------------------------
__global__ void zero_cnt_kernel() {
    int i = blockIdx.x * blockDim.x + threadIdx.x;
    if (i < NN) g_cnt[i] = 0;
}

__global__ void count_kernel(const int* __restrict__ dst) {
    int e = blockIdx.x * blockDim.x + threadIdx.x;
    if (e < NE) atomicAdd(&g_cnt[dst[e]], 1);
}

__global__ __launch_bounds__(1024) void scan_kernel() {
    __shared__ int s[1024];
    int t = threadIdx.x;
    int lo = t * 20;
    int hi = lo + 20; if (hi > NN) hi = NN;
    int sum = 0;
    for (int i = lo; i < hi; i++) sum += g_cnt[i];
    s[t] = sum;
    __syncthreads();
    for (int off = 1; off < 1024; off <<= 1) {
        int v = (t >= off) ? s[t - off] : 0;
        __syncthreads();
        s[t] += v;
        __syncthreads();
    }
    int run = s[t] - sum;
    for (int i = lo; i < hi; i++) {
        g_base[i] = run;
        g_cur[i] = run;
        run += g_cnt[i];
    }
    if (t == 0) g_base[NN] = NE;
}

__global__ void fill_kernel(const int* __restrict__ src, const int* __restrict__ dst) {
    int e = blockIdx.x * blockDim.x + threadIdx.x;
    if (e < NE) {
        int p = atomicAdd(&g_cur[dst[e]], 1);
        g_srcbyd[p] = src[e];
    }
}

// ------- fused edge kernel: one warp per NODE, all 8 heads at once -----------
// lane owns dims [lane*8, lane*8+8); head of lane = lane>>2; per-head score
// reduces within a 4-lane group (2 shfls).
__global__ __launch_bounds__(256) void fused_edge_kernel(const float* __restrict__ attn,
                                                         int do_pack)
{
    int n = blockIdx.x * 8 + (threadIdx.x >> 5);
    int lane = threadIdx.x & 31;
    if (n >= NN) return;
    const size_t rowoff = (size_t)n * HID + lane * 8;

    float fdv[8], av[8];
    {
        float4 t0 = *(const float4*)(g_fd + rowoff);
        float4 t1 = *(const float4*)(g_fd + rowoff + 4);
        fdv[0]=t0.x; fdv[1]=t0.y; fdv[2]=t0.z; fdv[3]=t0.w;
        fdv[4]=t1.x; fdv[5]=t1.y; fdv[6]=t1.z; fdv[7]=t1.w;
        float4 a0 = *(const float4*)(attn + lane * 8);
        float4 a1 = *(const float4*)(attn + lane * 8 + 4);
        av[0]=a0.x; av[1]=a0.y; av[2]=a0.z; av[3]=a0.w;
        av[4]=a1.x; av[5]=a1.y; av[6]=a1.z; av[7]=a1.w;
    }

    const int b  = g_base[n];
    const int e2 = g_base[n + 1];

    float m = -1e30f, sd = 0.f;
    float acc[8] = {0.f,0.f,0.f,0.f,0.f,0.f,0.f,0.f};

    for (int j = b; j < e2; j++) {
        int s = g_srcbyd[j];
        const float4* fp = (const float4*)(g_fs + (size_t)s * HID + lane * 8);
        float4 a0 = fp[0], a1 = fp[1];
        float fsv[8] = {a0.x,a0.y,a0.z,a0.w,a1.x,a1.y,a1.z,a1.w};
        float pp = 0.f;
        #pragma unroll
        for (int q = 0; q < 8; q++) {
            float v = fsv[q] + fdv[q];
            v = (v > 0.f) ? v : SLOPE * v;
            pp = fmaf(v, av[q], pp);
        }
        pp += __shfl_xor_sync(0xffffffffu, pp, 1);
        pp += __shfl_xor_sync(0xffffffffu, pp, 2);
        float nm = fmaxf(m, pp);
        float fac = __expf(m - nm);
        float w   = __expf(pp - nm);
        sd = sd * fac + w;
        #pragma unroll
        for (int q = 0; q < 8; q++) acc[q] = fmaf(acc[q], fac, w * fsv[q]);
        m = nm;
    }

    float inv = (sd > 0.f) ? 1.f / sd : 0.f;
    float hv[8];
    {
        float4 h0 = *(const float4*)(g_h + rowoff);
        float4 h1 = *(const float4*)(g_h + rowoff + 4);
        float hold[8] = {h0.x,h0.y,h0.z,h0.w,h1.x,h1.y,h1.z,h1.w};
        #pragma unroll
        for (int q = 0; q < 8; q++) hv[q] = fmaxf(fmaf(acc[q], inv, hold[q]), 0.f);
    }
    *(float4*)(g_h + rowoff)     = make_float4(hv[0], hv[1], hv[2], hv[3]);
    *(float4*)(g_h + rowoff + 4) = make_float4(hv[4], hv[5], hv[6], hv[7]);
    if (do_pack) {
        size_t pbase = rowoff >> 1;
        #pragma unroll
        for (int q = 0; q < 8; q += 2) {
            unsigned hi, lo;
            split_pack(hv[q], hv[q + 1], hi, lo);
            g_ah_hi[pbase + (q >> 1)] = hi;
            g_ah_lo[pbase + (q >> 1)] = lo;
        }
    }
}

// ---------------- graph boundaries (graph_ids is sorted) ---------------------
__global__ void gbound_kernel(const int* __restrict__ gids) {
    int g = threadIdx.x;
    if (g > NG) return;
    int lo = 0, hi = NN;
    while (lo < hi) {
        int mid = (lo + hi) >> 1;
        if (gids[mid] < g) lo = mid + 1; else hi = mid;
    }
    g_gstart[g] = lo;
}

// ---------------- pooling: segmented sum, no atomics -------------------------
__global__ __launch_bounds__(128) void pool_kernel(void) {
    int g = blockIdx.x;
    int c = blockIdx.y * 128 + threadIdx.x;
    int n0 = g_gstart[g], n1 = g_gstart[g + 1];
    float s = 0.f;
    int n = n0;
    for (; n + 4 <= n1; n += 4) {
        float a0 = g_h[(size_t)(n + 0) * HID + c];
        float a1 = g_h[(size_t)(n + 1) * HID + c];
        float a2 = g_h[(size_t)(n + 2) * HID + c];
        float a3 = g_h[(size_t)(n + 3) * HID + c];
        s += (a0 + a1) + (a2 + a3);
    }
    for (; n < n1; n++) s += g_h[(size_t)n * HID + c];
    g_hg[g * HID + c] = s;
}

// ---------------- small FC -----------------------------------------------------
__global__ void fc_kernel(const float* __restrict__ X, const float* __restrict__ W,
                          const float* __restrict__ b, float* __restrict__ Y,
                          int N, int K, int do_relu)
{
    __shared__ float xs[256];
    int row = blockIdx.x;
    for (int i = threadIdx.x; i < K; i += blockDim.x) xs[i] = X[row * K + i];
    __syncthreads();
    int col = threadIdx.x;
    if (col < N) {
        float s = b[col];
        for (int k = 0; k < K; k++) s = fmaf(xs[k], W[k * N + col], s);
        if (do_relu) s = fmaxf(s, 0.f);
        Y[row * N + col] = s;
    }
}

// ---------------- launch -------------------------------------------------------
extern "C" void kernel_launch(void* const* d_in, const int* in_sizes, int n_in,
                              void* d_out, int out_size)
{
    const float* feature   = (const float*)d_in[0];
    const float* W_in      = (const float*)d_in[1];
    const float* b_in      = (const float*)d_in[2];
    const float* W_src     = (const float*)d_in[3];
    const float* b_src     = (const float*)d_in[4];
    const float* W_dst     = (const float*)d_in[5];
    const float* b_dst     = (const float*)d_in[6];
    const float* attn      = (const float*)d_in[7];
    const float* Wc1       = (const float*)d_in[8];
    const float* bc1       = (const float*)d_in[9];
    const float* Wc2       = (const float*)d_in[10];
    const float* bc2       = (const float*)d_in[11];
    const float* Wc3       = (const float*)d_in[12];
    const float* bc3       = (const float*)d_in[13];
    const int*   src       = (const int*)d_in[14];
    const int*   dst       = (const int*)d_in[15];
    const int*   graph_ids = (const int*)d_in[16];
    float* out = (float*)d_out;

    float *p_h, *p_fs, *p_fd, *p_hg, *p_x1, *p_x2;
    unsigned *p_ah_hi, *p_ah_lo, *p_af_hi, *p_af_lo;
    unsigned *p_win_hi, *p_win_lo, *p_ws_hi, *p_ws_lo, *p_wd_hi, *p_wd_lo;
    cudaGetSymbolAddress((void**)&p_h,  g_h);
    cudaGetSymbolAddress((void**)&p_fs, g_fs);
    cudaGetSymbolAddress((void**)&p_fd, g_fd);
    cudaGetSymbolAddress((void**)&p_hg, g_hg);
    cudaGetSymbolAddress((void**)&p_x1, g_x1);
    cudaGetSymbolAddress((void**)&p_x2, g_x2);
    cudaGetSymbolAddress((void**)&p_ah_hi, g_ah_hi);
    cudaGetSymbolAddress((void**)&p_ah_lo, g_ah_lo);
    cudaGetSymbolAddress((void**)&p_af_hi, g_af_hi);
    cudaGetSymbolAddress((void**)&p_af_lo, g_af_lo);
    cudaGetSymbolAddress((void**)&p_win_hi, g_win_hi);
    cudaGetSymbolAddress((void**)&p_win_lo, g_win_lo);
    cudaGetSymbolAddress((void**)&p_ws_hi, g_ws_hi);
    cudaGetSymbolAddress((void**)&p_ws_lo, g_ws_lo);
    cudaGetSymbolAddress((void**)&p_wd_hi, g_wd_hi);
    cudaGetSymbolAddress((void**)&p_wd_lo, g_wd_lo);

    // CSR by dst + graph boundaries
    zero_cnt_kernel<<<(NN + 255) / 256, 256>>>();
    count_kernel<<<(NE + 255) / 256, 256>>>(dst);
    scan_kernel<<<1, 1024>>>();
    fill_kernel<<<(NE + 255) / 256, 256>>>(src, dst);
    gbound_kernel<<<1, 128>>>(graph_ids);

    // pack weights + feature
    const int WIN_P = (INDIM / 2) * HID;
    const int WL_P  = (HID / 2) * HID;
    pack_w_kernel<<<(WIN_P + 255) / 256, 256>>>(W_in, p_win_hi, p_win_lo, INDIM / 2, HID);
    for (int l = 0; l < LAYERS; l++) {
        pack_w_kernel<<<(WL_P + 255) / 256, 256>>>(W_src + (size_t)l * HID * HID,
            p_ws_hi + (size_t)l * WL_P, p_ws_lo + (size_t)l * WL_P, HID / 2, HID);
        pack_w_kernel<<<(WL_P + 255) / 256, 256>>>(W_dst + (size_t)l * HID * HID,
            p_wd_hi + (size_t)l * WL_P, p_wd_lo + (size_t)l * WL_P, HID / 2, HID);
    }
    pack_rows_kernel<<<(NN * INDIM / 2 + 255) / 256, 256>>>(feature, p_af_hi, p_af_lo, NN * INDIM / 2);

    const int MROWS = (NN + GBM - 1) / GBM;
    dim3 grid1(HID / GBN, MROWS);
    dim3 grid2(2 * (HID / GBN), MROWS);

    gemm_bf16x3_kernel<<<grid1, 256>>>(
        p_af_hi, p_af_lo, p_win_hi, p_win_lo, p_win_hi, p_win_lo,
        b_in, b_in, p_h, p_h, p_ah_hi, p_ah_lo,
        NN, HID, INDIM / 2, HID / GBN, 1);

    const int fused_blocks = (NN + 7) / 8;   // warp per node

    for (int l = 0; l < LAYERS; l++) {
        const float* bs = b_src + (size_t)l * HID;
        const float* bd = b_dst + (size_t)l * HID;
        const float* al = attn + (size_t)l * HEADS * DH;

        gemm_bf16x3_kernel<<<grid2, 256>>>(
            p_ah_hi, p_ah_lo,
            p_ws_hi + (size_t)l * WL_P, p_ws_lo + (size_t)l * WL_P,
            p_wd_hi + (size_t)l * WL_P, p_wd_lo + (size_t)l * WL_P,
            bs, bd, p_fs, p_fd, (unsigned*)0, (unsigned*)0,
            NN, HID, HID / 2, HID / GBN, 0);

        fused_edge_kernel<<<fused_blocks, 256>>>(al, (l + 1 < LAYERS) ? 1 : 0);
    }

    dim3 pgrid(NG, 2);
    pool_kernel<<<pgrid, 128>>>();

    fc_kernel<<<NG, 256>>>(p_hg, Wc1, bc1, p_x1, HID, HID, 1);
    fc_kernel<<<NG, 256>>>(p_x1, Wc2, bc2, p_x2, HID / 2, HID, 1);
    fc_kernel<<<NG, 256>>>(p_x2, Wc3, bc3, out, OUTDIM, HID / 2, 0);
}

// round 6
// speedup vs baseline: 3.3593x; 1.0398x over previous
#include <cuda_runtime.h>
#include <cuda_bf16.h>
#include <math.h>

#define NN      20000
#define NE      320000
#define INDIM   128
#define HID     256
#define HEADS   8
#define DH      32
#define LAYERS  3
#define NG      64
#define OUTDIM  10
#define SLOPE   0.2f

#define WIN_P ((INDIM / 2) * HID)
#define WL_P  ((HID / 2) * HID)

// ---------------- scratch (device globals; no allocation allowed) ----------
__device__ float g_h[NN * HID];
__device__ float g_fs[NN * HID];
__device__ float g_fd[NN * HID];
__device__ float g_hg[NG * HID];
__device__ float g_x1[NG * HID];
__device__ float g_x2[NG * (HID / 2)];
// packed bf16 pair buffers (hi/lo split)
__device__ unsigned g_ah_hi[NN * HID / 2];
__device__ unsigned g_ah_lo[NN * HID / 2];
__device__ unsigned g_af_hi[NN * INDIM / 2];
__device__ unsigned g_af_lo[NN * INDIM / 2];
__device__ unsigned g_win_hi[WIN_P], g_win_lo[WIN_P];
__device__ unsigned g_ws_hi[LAYERS * WL_P], g_ws_lo[LAYERS * WL_P];
__device__ unsigned g_wd_hi[LAYERS * WL_P], g_wd_lo[LAYERS * WL_P];
// CSR by dst
__device__ int g_cnt[NN];
__device__ int g_base[NN + 1];
__device__ int g_cur[NN];
__device__ int g_srcbyd[NE];
__device__ int g_gstart[NG + 1];

// ---------------- bf16 pack helpers -----------------------------------------
__device__ __forceinline__ unsigned pack_bf2(__nv_bfloat16 a, __nv_bfloat16 b) {
    return ((unsigned)__bfloat16_as_ushort(b) << 16) | (unsigned)__bfloat16_as_ushort(a);
}

__device__ __forceinline__ void split_pack(float x0, float x1, unsigned& hi, unsigned& lo) {
    __nv_bfloat16 h0 = __float2bfloat16_rn(x0);
    __nv_bfloat16 h1 = __float2bfloat16_rn(x1);
    __nv_bfloat16 l0 = __float2bfloat16_rn(x0 - __bfloat162float(h0));
    __nv_bfloat16 l1 = __float2bfloat16_rn(x1 - __bfloat162float(h1));
    hi = pack_bf2(h0, h1);
    lo = pack_bf2(l0, l1);
}

__device__ __forceinline__ void mma_bf16(float c[4], const unsigned a[4], const unsigned b[2]) {
    asm volatile(
        "mma.sync.aligned.m16n8k16.row.col.f32.bf16.bf16.f32 "
        "{%0,%1,%2,%3}, {%4,%5,%6,%7}, {%8,%9}, {%0,%1,%2,%3};"
        : "+f"(c[0]), "+f"(c[1]), "+f"(c[2]), "+f"(c[3])
        : "r"(a[0]), "r"(a[1]), "r"(a[2]), "r"(a[3]), "r"(b[0]), "r"(b[1]));
}

__device__ __forceinline__ void ldsm_x4(unsigned r[4], unsigned addr) {
    asm volatile("ldmatrix.sync.aligned.m8n8.x4.shared.b16 {%0,%1,%2,%3}, [%4];"
        : "=r"(r[0]), "=r"(r[1]), "=r"(r[2]), "=r"(r[3]) : "r"(addr));
}

// ---------------- pack kernels ------------------------------------------------
__global__ void pack_rows_kernel(const float* __restrict__ X,
                                 unsigned* __restrict__ hi, unsigned* __restrict__ lo,
                                 int npairs)
{
    int i = blockIdx.x * blockDim.x + threadIdx.x;
    if (i >= npairs) return;
    float2 v = ((const float2*)X)[i];
    split_pack(v.x, v.y, hi[i], lo[i]);
}

// all weights in one launch
__global__ void pack_all_w_kernel(const float* __restrict__ W_in,
                                  const float* __restrict__ W_src,
                                  const float* __restrict__ W_dst)
{
    int i = blockIdx.x * blockDim.x + threadIdx.x;
    if (i < WIN_P) {
        int k2 = i / HID, n = i - k2 * HID;
        split_pack(W_in[(2 * k2) * HID + n], W_in[(2 * k2 + 1) * HID + n],
                   g_win_hi[i], g_win_lo[i]);
    } else {
        int j = i - WIN_P;
        if (j >= 2 * LAYERS * WL_P) return;
        int which = j / (LAYERS * WL_P);
        int rem = j - which * (LAYERS * WL_P);
        int l = rem / WL_P;
        int p = rem - l * WL_P;
        int k2 = p / HID, n = p - k2 * HID;
        const float* W = (which ? W_dst : W_src) + (size_t)l * HID * HID;
        unsigned* hi = (which ? g_wd_hi : g_ws_hi) + (size_t)l * WL_P;
        unsigned* lo = (which ? g_wd_lo : g_ws_lo) + (size_t)l * WL_P;
        split_pack(W[(2 * k2) * HID + n], W[(2 * k2 + 1) * HID + n], hi[p], lo[p]);
    }
}

// ---------------- bf16x3 tensor-core GEMM (double-buffered, ldmatrix A) ------
#define GBM 128
#define GBN 128
#define AST 12
#define BST 136

__global__ __launch_bounds__(256) void gemm_bf16x3_kernel(
    const unsigned* __restrict__ Ahi, const unsigned* __restrict__ Alo,
    const unsigned* __restrict__ B1hi, const unsigned* __restrict__ B1lo,
    const unsigned* __restrict__ B2hi, const unsigned* __restrict__ B2lo,
    const float* __restrict__ bias1, const float* __restrict__ bias2,
    float* __restrict__ C1, float* __restrict__ C2,
    unsigned* __restrict__ Pho, unsigned* __restrict__ Plo,
    int M, int N, int K2, int nb, int do_pack)
{
    __shared__ unsigned As_hi[2][GBM][AST];
    __shared__ unsigned As_lo[2][GBM][AST];
    __shared__ unsigned Bs_hi[2][8][BST];
    __shared__ unsigned Bs_lo[2][8][BST];

    int bx = blockIdx.x;
    int which = 0;
    if (bx >= nb) { which = 1; bx -= nb; }
    const unsigned* Bhi = which ? B2hi : B1hi;
    const unsigned* Blo = which ? B2lo : B1lo;
    const float* bias   = which ? bias2 : bias1;
    float* C            = which ? C2 : C1;

    const int tid  = threadIdx.x;
    const int wid  = tid >> 5;
    const int lane = tid & 31;
    const int wm   = (wid >> 2) * 64;
    const int wn   = (wid & 3) * 32;
    const int grp  = lane >> 2;
    const int tig  = lane & 3;
    const int row0 = blockIdx.y * GBM;
    const int col0 = bx * GBN;

    const int ar = tid >> 1;
    const int ac = (tid & 1) * 4;
    const int brr = tid >> 5;
    const int bcc = (tid & 31) * 4;

    const bool a_ok = (row0 + ar) < M;
    const size_t a_off = (size_t)(row0 + ar) * K2 + ac;

    // ldmatrix lane addressing: row = wm + mt*16 + (lane&15), word-col = (lane>>4)*4
    const int lrow = wm + (lane & 15);
    const int lcol = (lane >> 4) * 4;
    const unsigned sa_hi = (unsigned)__cvta_generic_to_shared(&As_hi[0][0][0]);
    const unsigned sa_lo = (unsigned)__cvta_generic_to_shared(&As_lo[0][0][0]);

    float c[4][4][4];
    #pragma unroll
    for (int i = 0; i < 4; i++)
        #pragma unroll
        for (int j = 0; j < 4; j++)
            #pragma unroll
            for (int k = 0; k < 4; k++) c[i][j][k] = 0.f;

    uint4 vah = make_uint4(0,0,0,0), val_ = vah, vbh, vbl;

    if (a_ok) {
        vah = *(const uint4*)(Ahi + a_off);
        val_ = *(const uint4*)(Alo + a_off);
    }
    vbh = *(const uint4*)(Bhi + (size_t)brr * N + col0 + bcc);
    vbl = *(const uint4*)(Blo + (size_t)brr * N + col0 + bcc);
    *(uint4*)&As_hi[0][ar][ac] = vah;
    *(uint4*)&As_lo[0][ar][ac] = val_;
    *(uint4*)&Bs_hi[0][brr][bcc] = vbh;
    *(uint4*)&Bs_lo[0][brr][bcc] = vbl;
    __syncthreads();

    const int nk = K2 >> 3;
    for (int t = 0; t < nk; t++) {
        const int cb = t & 1;
        const bool more = (t + 1 < nk);
        if (more) {
            int kp = (t + 1) * 8;
            if (a_ok) {
                vah = *(const uint4*)(Ahi + a_off + kp);
                val_ = *(const uint4*)(Alo + a_off + kp);
            }
            vbh = *(const uint4*)(Bhi + (size_t)(kp + brr) * N + col0 + bcc);
            vbl = *(const uint4*)(Blo + (size_t)(kp + brr) * N + col0 + bcc);
        }

        unsigned ah[4][4], al[4][4], bh[4][2], bl[4][2];
        #pragma unroll
        for (int mt = 0; mt < 4; mt++) {
            unsigned off = (((unsigned)(cb * GBM + lrow + mt * 16)) * AST + lcol) * 4u;
            ldsm_x4(ah[mt], sa_hi + off);
            ldsm_x4(al[mt], sa_lo + off);
        }
        #pragma unroll
        for (int nt = 0; nt < 4; nt++) {
            int cn = wn + nt * 8 + grp;
            bh[nt][0] = Bs_hi[cb][tig][cn];     bh[nt][1] = Bs_hi[cb][tig + 4][cn];
            bl[nt][0] = Bs_lo[cb][tig][cn];     bl[nt][1] = Bs_lo[cb][tig + 4][cn];
        }
        #pragma unroll
        for (int mt = 0; mt < 4; mt++)
            #pragma unroll
            for (int nt = 0; nt < 4; nt++) {
                mma_bf16(c[mt][nt], ah[mt], bl[nt]);
                mma_bf16(c[mt][nt], al[mt], bh[nt]);
                mma_bf16(c[mt][nt], ah[mt], bh[nt]);
            }

        if (more) {
            *(uint4*)&As_hi[1 - cb][ar][ac] = vah;
            *(uint4*)&As_lo[1 - cb][ar][ac] = val_;
            *(uint4*)&Bs_hi[1 - cb][brr][bcc] = vbh;
            *(uint4*)&Bs_lo[1 - cb][brr][bcc] = vbl;
            __syncthreads();
        }
    }

    #pragma unroll
    for (int nt = 0; nt < 4; nt++) {
        int cc = col0 + wn + nt * 8 + 2 * tig;
        float b0 = bias[cc], b1 = bias[cc + 1];
        #pragma unroll
        for (int mt = 0; mt < 4; mt++) {
            int r0 = row0 + wm + mt * 16 + grp;
            if (r0 < M) {
                float v0 = c[mt][nt][0] + b0, v1 = c[mt][nt][1] + b1;
                *(float2*)(C + (size_t)r0 * N + cc) = make_float2(v0, v1);
                if (do_pack && which == 0) {
                    unsigned hi, lo;
                    split_pack(v0, v1, hi, lo);
                    size_t pi = ((size_t)r0 * N + cc) >> 1;
                    Pho[pi] = hi; Plo[pi] = lo;
                }
            }
            int r1 = r0 + 8;
            if (r1 < M) {
                float v0 = c[mt][nt][2] + b0, v1 = c[mt][nt][3] + b1;
                *(float2*)(C + (size_t)r1 * N + cc) = make_float2(v0, v1);
                if (do_pack && which == 0) {
                    unsigned hi, lo;
                    split_pack(v0, v1, hi, lo);
                    size_t pi = ((size_t)r1 * N + cc) >> 1;
                    Pho[pi] = hi; Plo[pi] = lo;
                }
            }
        }
    }
}

// ---------------- CSR build (once per launch) --------------------------------
__global__ void zero_cnt_kernel() {
    int i = blockIdx.x * blockDim.x + threadIdx.x;
    if (i < NN) g_cnt[i] = 0;
}

__global__ void count_kernel(const int* __restrict__ dst) {
    int e = blockIdx.x * blockDim.x + threadIdx.x;
    if (e < NE) atomicAdd(&g_cnt[dst[e]], 1);
}

__global__ __launch_bounds__(1024) void scan_kernel() {
    __shared__ int s[1024];
    int t = threadIdx.x;
    int lo = t * 20;
    int hi = lo + 20; if (hi > NN) hi = NN;
    int sum = 0;
    for (int i = lo; i < hi; i++) sum += g_cnt[i];
    s[t] = sum;
    __syncthreads();
    for (int off = 1; off < 1024; off <<= 1) {
        int v = (t >= off) ? s[t - off] : 0;
        __syncthreads();
        s[t] += v;
        __syncthreads();
    }
    int run = s[t] - sum;
    for (int i = lo; i < hi; i++) {
        g_base[i] = run;
        g_cur[i] = run;
        run += g_cnt[i];
    }
    if (t == 0) g_base[NN] = NE;
}

__global__ void fill_kernel(const int* __restrict__ src, const int* __restrict__ dst) {
    int e = blockIdx.x * blockDim.x + threadIdx.x;
    if (e < NE) {
        int p = atomicAdd(&g_cur[dst[e]], 1);
        g_srcbyd[p] = src[e];
    }
}

// ------- fused edge kernel: one warp per NODE, all 8 heads at once -----------
__global__ __launch_bounds__(256) void fused_edge_kernel(const float* __restrict__ attn,
                                                         int do_pack)
{
    int n = blockIdx.x * 8 + (threadIdx.x >> 5);
    int lane = threadIdx.x & 31;
    if (n >= NN) return;
    const size_t rowoff = (size_t)n * HID + lane * 8;

    float fdv[8], av[8];
    {
        float4 t0 = *(const float4*)(g_fd + rowoff);
        float4 t1 = *(const float4*)(g_fd + rowoff + 4);
        fdv[0]=t0.x; fdv[1]=t0.y; fdv[2]=t0.z; fdv[3]=t0.w;
        fdv[4]=t1.x; fdv[5]=t1.y; fdv[6]=t1.z; fdv[7]=t1.w;
        float4 a0 = *(const float4*)(attn + lane * 8);
        float4 a1 = *(const float4*)(attn + lane * 8 + 4);
        av[0]=a0.x; av[1]=a0.y; av[2]=a0.z; av[3]=a0.w;
        av[4]=a1.x; av[5]=a1.y; av[6]=a1.z; av[7]=a1.w;
    }

    const int b  = g_base[n];
    const int e2 = g_base[n + 1];

    float m = -1e30f, sd = 0.f;
    float acc[8] = {0.f,0.f,0.f,0.f,0.f,0.f,0.f,0.f};

    for (int j = b; j < e2; j++) {
        int s = g_srcbyd[j];
        const float4* fp = (const float4*)(g_fs + (size_t)s * HID + lane * 8);
        float4 a0 = fp[0], a1 = fp[1];
        float fsv[8] = {a0.x,a0.y,a0.z,a0.w,a1.x,a1.y,a1.z,a1.w};
        float pp = 0.f;
        #pragma unroll
        for (int q = 0; q < 8; q++) {
            float v = fsv[q] + fdv[q];
            v = (v > 0.f) ? v : SLOPE * v;
            pp = fmaf(v, av[q], pp);
        }
        pp += __shfl_xor_sync(0xffffffffu, pp, 1);
        pp += __shfl_xor_sync(0xffffffffu, pp, 2);
        float nm = fmaxf(m, pp);
        float fac = __expf(m - nm);
        float w   = __expf(pp - nm);
        sd = sd * fac + w;
        #pragma unroll
        for (int q = 0; q < 8; q++) acc[q] = fmaf(acc[q], fac, w * fsv[q]);
        m = nm;
    }

    float inv = (sd > 0.f) ? 1.f / sd : 0.f;
    float hv[8];
    {
        float4 h0 = *(const float4*)(g_h + rowoff);
        float4 h1 = *(const float4*)(g_h + rowoff + 4);
        float hold[8] = {h0.x,h0.y,h0.z,h0.w,h1.x,h1.y,h1.z,h1.w};
        #pragma unroll
        for (int q = 0; q < 8; q++) hv[q] = fmaxf(fmaf(acc[q], inv, hold[q]), 0.f);
    }
    *(float4*)(g_h + rowoff)     = make_float4(hv[0], hv[1], hv[2], hv[3]);
    *(float4*)(g_h + rowoff + 4) = make_float4(hv[4], hv[5], hv[6], hv[7]);
    if (do_pack) {
        size_t pbase = rowoff >> 1;
        #pragma unroll
        for (int q = 0; q < 8; q += 2) {
            unsigned hi, lo;
            split_pack(hv[q], hv[q + 1], hi, lo);
            g_ah_hi[pbase + (q >> 1)] = hi;
            g_ah_lo[pbase + (q >> 1)] = lo;
        }
    }
}

// ---------------- graph boundaries (graph_ids is sorted) ---------------------
__global__ void gbound_kernel(const int* __restrict__ gids) {
    int g = threadIdx.x;
    if (g > NG) return;
    int lo = 0, hi = NN;
    while (lo < hi) {
        int mid = (lo + hi) >> 1;
        if (gids[mid] < g) lo = mid + 1; else hi = mid;
    }
    g_gstart[g] = lo;
}

// ---------------- pooling: segmented sum, no atomics -------------------------
__global__ __launch_bounds__(128) void pool_kernel(void) {
    int g = blockIdx.x;
    int c = blockIdx.y * 128 + threadIdx.x;
    int n0 = g_gstart[g], n1 = g_gstart[g + 1];
    float s = 0.f;
    int n = n0;
    for (; n + 4 <= n1; n += 4) {
        float a0 = g_h[(size_t)(n + 0) * HID + c];
        float a1 = g_h[(size_t)(n + 1) * HID + c];
        float a2 = g_h[(size_t)(n + 2) * HID + c];
        float a3 = g_h[(size_t)(n + 3) * HID + c];
        s += (a0 + a1) + (a2 + a3);
    }
    for (; n < n1; n++) s += g_h[(size_t)n * HID + c];
    g_hg[g * HID + c] = s;
}

// ---------------- small FC -----------------------------------------------------
__global__ void fc_kernel(const float* __restrict__ X, const float* __restrict__ W,
                          const float* __restrict__ b, float* __restrict__ Y,
                          int N, int K, int do_relu)
{
    __shared__ float xs[256];
    int row = blockIdx.x;
    for (int i = threadIdx.x; i < K; i += blockDim.x) xs[i] = X[row * K + i];
    __syncthreads();
    int col = threadIdx.x;
    if (col < N) {
        float s = b[col];
        for (int k = 0; k < K; k++) s = fmaf(xs[k], W[k * N + col], s);
        if (do_relu) s = fmaxf(s, 0.f);
        Y[row * N + col] = s;
    }
}

// ---------------- launch -------------------------------------------------------
extern "C" void kernel_launch(void* const* d_in, const int* in_sizes, int n_in,
                              void* d_out, int out_size)
{
    const float* feature   = (const float*)d_in[0];
    const float* W_in      = (const float*)d_in[1];
    const float* b_in      = (const float*)d_in[2];
    const float* W_src     = (const float*)d_in[3];
    const float* b_src     = (const float*)d_in[4];
    const float* W_dst     = (const float*)d_in[5];
    const float* b_dst     = (const float*)d_in[6];
    const float* attn      = (const float*)d_in[7];
    const float* Wc1       = (const float*)d_in[8];
    const float* bc1       = (const float*)d_in[9];
    const float* Wc2       = (const float*)d_in[10];
    const float* bc2       = (const float*)d_in[11];
    const float* Wc3       = (const float*)d_in[12];
    const float* bc3       = (const float*)d_in[13];
    const int*   src       = (const int*)d_in[14];
    const int*   dst       = (const int*)d_in[15];
    const int*   graph_ids = (const int*)d_in[16];
    float* out = (float*)d_out;

    float *p_h, *p_fs, *p_fd, *p_hg, *p_x1, *p_x2;
    unsigned *p_ah_hi, *p_ah_lo, *p_af_hi, *p_af_lo;
    unsigned *p_win_hi, *p_win_lo, *p_ws_hi, *p_ws_lo, *p_wd_hi, *p_wd_lo;
    cudaGetSymbolAddress((void**)&p_h,  g_h);
    cudaGetSymbolAddress((void**)&p_fs, g_fs);
    cudaGetSymbolAddress((void**)&p_fd, g_fd);
    cudaGetSymbolAddress((void**)&p_hg, g_hg);
    cudaGetSymbolAddress((void**)&p_x1, g_x1);
    cudaGetSymbolAddress((void**)&p_x2, g_x2);
    cudaGetSymbolAddress((void**)&p_ah_hi, g_ah_hi);
    cudaGetSymbolAddress((void**)&p_ah_lo, g_ah_lo);
    cudaGetSymbolAddress((void**)&p_af_hi, g_af_hi);
    cudaGetSymbolAddress((void**)&p_af_lo, g_af_lo);
    cudaGetSymbolAddress((void**)&p_win_hi, g_win_hi);
    cudaGetSymbolAddress((void**)&p_win_lo, g_win_lo);
    cudaGetSymbolAddress((void**)&p_ws_hi, g_ws_hi);
    cudaGetSymbolAddress((void**)&p_ws_lo, g_ws_lo);
    cudaGetSymbolAddress((void**)&p_wd_hi, g_wd_hi);
    cudaGetSymbolAddress((void**)&p_wd_lo, g_wd_lo);

    // 1-5: packs + CSR prologue (so launch #6 is a GEMM for ncu -s 5 -c 1)
    const int ALLW = WIN_P + 2 * LAYERS * WL_P;
    pack_all_w_kernel<<<(ALLW + 255) / 256, 256>>>(W_in, W_src, W_dst);
    pack_rows_kernel<<<(NN * INDIM / 2 + 255) / 256, 256>>>(feature, p_af_hi, p_af_lo, NN * INDIM / 2);
    zero_cnt_kernel<<<(NN + 255) / 256, 256>>>();
    count_kernel<<<(NE + 255) / 256, 256>>>(dst);
    scan_kernel<<<1, 1024>>>();

    const int MROWS = (NN + GBM - 1) / GBM;
    dim3 grid1(HID / GBN, MROWS);
    dim3 grid2(2 * (HID / GBN), MROWS);

    // 6: input GEMM (ncu capture target)
    gemm_bf16x3_kernel<<<grid1, 256>>>(
        p_af_hi, p_af_lo, p_win_hi, p_win_lo, p_win_hi, p_win_lo,
        b_in, b_in, p_h, p_h, p_ah_hi, p_ah_lo,
        NN, HID, INDIM / 2, HID / GBN, 1);

    fill_kernel<<<(NE + 255) / 256, 256>>>(src, dst);
    gbound_kernel<<<1, 128>>>(graph_ids);

    const int fused_blocks = (NN + 7) / 8;

    for (int l = 0; l < LAYERS; l++) {
        const float* bs = b_src + (size_t)l * HID;
        const float* bd = b_dst + (size_t)l * HID;
        const float* al = attn + (size_t)l * HEADS * DH;

        gemm_bf16x3_kernel<<<grid2, 256>>>(
            p_ah_hi, p_ah_lo,
            p_ws_hi + (size_t)l * WL_P, p_ws_lo + (size_t)l * WL_P,
            p_wd_hi + (size_t)l * WL_P, p_wd_lo + (size_t)l * WL_P,
            bs, bd, p_fs, p_fd, (unsigned*)0, (unsigned*)0,
            NN, HID, HID / 2, HID / GBN, 0);

        fused_edge_kernel<<<fused_blocks, 256>>>(al, (l + 1 < LAYERS) ? 1 : 0);
    }

    dim3 pgrid(NG, 2);
    pool_kernel<<<pgrid, 128>>>();

    fc_kernel<<<NG, 256>>>(p_hg, Wc1, bc1, p_x1, HID, HID, 1);
    fc_kernel<<<NG, 256>>>(p_x1, Wc2, bc2, p_x2, HID / 2, HID, 1);
    fc_kernel<<<NG, 256>>>(p_x2, Wc3, bc3, out, OUTDIM, HID / 2, 0);
}

// round 9
// speedup vs baseline: 3.5067x; 1.0439x over previous
#include <cuda_runtime.h>
#include <cuda_bf16.h>
#include <math.h>

#define NN      20000
#define NE      320000
#define INDIM   128
#define HID     256
#define HEADS   8
#define DH      32
#define LAYERS  3
#define NG      64
#define OUTDIM  10
#define SLOPE   0.2f

#define K2IN  (INDIM / 2)        // 64 pairs per feature row
#define K2L   (HID / 2)          // 128 pairs per h row
#define WIN_P (K2IN * HID)       // W_in packed [K2=64][N=256]
#define WL_P  (K2L * HID)        // layer W packed [K2=128][N=256]

// ---------------- scratch (device globals; no allocation allowed) ----------
__device__ float g_h[NN * HID];
__device__ float g_fs[NN * HID];
__device__ float g_fd[NN * HID];
// packed bf16 pair buffers (hi/lo split); [row][k2] K-contiguous
__device__ unsigned g_ah_hi[NN * K2L];
__device__ unsigned g_ah_lo[NN * K2L];
__device__ unsigned g_af_hi[NN * K2IN];
__device__ unsigned g_af_lo[NN * K2IN];
// weights packed [K2][N]
__device__ unsigned g_win_hi[WIN_P], g_win_lo[WIN_P];
__device__ unsigned g_ws_hi[LAYERS * WL_P], g_ws_lo[LAYERS * WL_P];
__device__ unsigned g_wd_hi[LAYERS * WL_P], g_wd_lo[LAYERS * WL_P];
// CSR by dst
__device__ int g_cnt[NN];
__device__ int g_base[NN + 1];
__device__ int g_cur[NN];
__device__ int g_srcbyd[NE];
__device__ int g_gstart[NG + 1];

// ---------------- bf16 pack helpers -----------------------------------------
__device__ __forceinline__ unsigned pack_bf2(__nv_bfloat16 a, __nv_bfloat16 b) {
    return ((unsigned)__bfloat16_as_ushort(b) << 16) | (unsigned)__bfloat16_as_ushort(a);
}

__device__ __forceinline__ void split_pack(float x0, float x1, unsigned& hi, unsigned& lo) {
    __nv_bfloat16 h0 = __float2bfloat16_rn(x0);
    __nv_bfloat16 h1 = __float2bfloat16_rn(x1);
    __nv_bfloat16 l0 = __float2bfloat16_rn(x0 - __bfloat162float(h0));
    __nv_bfloat16 l1 = __float2bfloat16_rn(x1 - __bfloat162float(h1));
    hi = pack_bf2(h0, h1);
    lo = pack_bf2(l0, l1);
}

__device__ __forceinline__ void mma_bf16(float c[4], const unsigned a[4], const unsigned b[2]) {
    asm volatile(
        "mma.sync.aligned.m16n8k16.row.col.f32.bf16.bf16.f32 "
        "{%0,%1,%2,%3}, {%4,%5,%6,%7}, {%8,%9}, {%0,%1,%2,%3};"
        : "+f"(c[0]), "+f"(c[1]), "+f"(c[2]), "+f"(c[3])
        : "r"(a[0]), "r"(a[1]), "r"(a[2]), "r"(a[3]), "r"(b[0]), "r"(b[1]));
}

__device__ __forceinline__ void ldsm_x4(unsigned r[4], unsigned addr) {
    asm volatile("ldmatrix.sync.aligned.m8n8.x4.shared.b16 {%0,%1,%2,%3}, [%4];"
        : "=r"(r[0]), "=r"(r[1]), "=r"(r[2]), "=r"(r[3]) : "r"(addr));
}

// ---------------- pack everything in one launch -------------------------------
__global__ void pack_all_kernel(const float* __restrict__ W_in,
                                const float* __restrict__ W_src,
                                const float* __restrict__ W_dst,
                                const float* __restrict__ feature)
{
    int i = blockIdx.x * blockDim.x + threadIdx.x;
    const int NF = NN * K2IN;
    if (i < NF) {
        float2 v = ((const float2*)feature)[i];
        split_pack(v.x, v.y, g_af_hi[i], g_af_lo[i]);
        return;
    }
    int j = i - NF;
    if (j < WIN_P) {
        int k2 = j >> 8, n = j & 255;
        split_pack(W_in[(2 * k2) * HID + n], W_in[(2 * k2 + 1) * HID + n],
                   g_win_hi[j], g_win_lo[j]);
        return;
    }
    j -= WIN_P;
    if (j >= 2 * LAYERS * WL_P) return;
    int which = j / (LAYERS * WL_P);
    int rem = j - which * (LAYERS * WL_P);
    int l = rem / WL_P;
    int p = rem - l * WL_P;
    int k2 = p >> 8, n = p & 255;
    const float* W = (which ? W_dst : W_src) + (size_t)l * HID * HID;
    unsigned* hi = (which ? g_wd_hi : g_ws_hi) + (size_t)l * WL_P;
    unsigned* lo = (which ? g_wd_lo : g_ws_lo) + (size_t)l * WL_P;
    split_pack(W[(2 * k2) * HID + n], W[(2 * k2 + 1) * HID + n], hi[p], lo[p]);
}

// ---------------- bf16x3 mma.sync GEMM, k-tile = 32, dynamic smem ------------
// C[M,256] = A[M,K]@B[K,256] + bias. A [row][K2] pairs; B [K2][256] pairs.
// grid.x in [0, 2*nb): nb N-tiles for C1, then nb for C2. nb = 256/GBN = 2.
#define GBM 128
#define GBN 128
#define AST 20                    // A row stride (16 data + 4 pad) u32
#define BST 136                   // B row stride u32
#define OFF_ALO 20480             // 2*128*20*4
#define OFF_BHI 40960
#define OFF_BLO 58368             // + 2*16*136*4
#define GSMEM   75776

__global__ __launch_bounds__(256) void gemm_bf16x3_kernel(
    const unsigned* __restrict__ Ahi, const unsigned* __restrict__ Alo,
    const unsigned* __restrict__ B1hi, const unsigned* __restrict__ B1lo,
    const unsigned* __restrict__ B2hi, const unsigned* __restrict__ B2lo,
    const float* __restrict__ bias1, const float* __restrict__ bias2,
    float* __restrict__ C1, float* __restrict__ C2,
    unsigned* __restrict__ Pho, unsigned* __restrict__ Plo,
    int M, int K2g, int nb, int do_pack)
{
    extern __shared__ __align__(16) unsigned char dsm[];
    unsigned* As_hi = (unsigned*)dsm;                    // [2][128][20]
    unsigned* As_lo = (unsigned*)(dsm + OFF_ALO);
    unsigned* Bs_hi = (unsigned*)(dsm + OFF_BHI);        // [2][16][136]
    unsigned* Bs_lo = (unsigned*)(dsm + OFF_BLO);

    int bx = blockIdx.x;
    int which = 0;
    if (bx >= nb) { which = 1; bx -= nb; }
    const unsigned* Bhi = which ? B2hi : B1hi;
    const unsigned* Blo = which ? B2lo : B1lo;
    const float* bias   = which ? bias2 : bias1;
    float* C            = which ? C2 : C1;

    const int tid  = threadIdx.x;
    const int wid  = tid >> 5;
    const int lane = tid & 31;
    const int wm   = (wid >> 2) * 64;
    const int wn   = (wid & 3) * 32;
    const int grp  = lane >> 2;
    const int tig  = lane & 3;
    const int row0 = blockIdx.y * GBM;
    const int col0 = bx * GBN;

    const int arw = tid >> 2;               // A row 0..63 (+64)
    const int asg = (tid & 3) * 4;          // A pair col 0,4,8,12
    const int brw = tid >> 5;               // B row 0..7 (+8)
    const int bcc = (tid & 31) * 4;         // B col

    const int lrow = wm + (lane & 15);
    const int lcol = (lane >> 4) * 4;
    const unsigned sa_hi = (unsigned)__cvta_generic_to_shared(As_hi);
    const unsigned sa_lo = (unsigned)__cvta_generic_to_shared(As_lo);

    float c[4][4][4];
    #pragma unroll
    for (int i = 0; i < 4; i++)
        #pragma unroll
        for (int j = 0; j < 4; j++)
            #pragma unroll
            for (int k = 0; k < 4; k++) c[i][j][k] = 0.f;

    uint4 vah[2], val2[2], vbh[2], vbl[2];

    #define LD_REGS(t) do {                                                    \
        int kb = (t) * 16;                                                     \
        _Pragma("unroll")                                                      \
        for (int i = 0; i < 2; i++) {                                          \
            int rw = arw + i * 64;                                             \
            bool ok = (row0 + rw) < M;                                         \
            size_t go = (size_t)(row0 + rw) * K2g + kb + asg;                  \
            vah[i] = make_uint4(0,0,0,0); val2[i] = vah[i];                    \
            if (ok) { vah[i] = *(const uint4*)(Ahi + go);                      \
                      val2[i] = *(const uint4*)(Alo + go); }                   \
            int rb = brw + i * 8;                                              \
            size_t gb = (size_t)(kb + rb) * 256 + col0 + bcc;                  \
            vbh[i] = *(const uint4*)(Bhi + gb);                                \
            vbl[i] = *(const uint4*)(Blo + gb);                                \
        }                                                                      \
    } while (0)

    #define ST_SMEM(s) do {                                                   \
        _Pragma("unroll")                                                      \
        for (int i = 0; i < 2; i++) {                                          \
            int rw = arw + i * 64;                                             \
            int ai = ((s) * 128 + rw) * AST + asg;                             \
            *(uint4*)(As_hi + ai) = vah[i];                                    \
            *(uint4*)(As_lo + ai) = val2[i];                                   \
            int rb = brw + i * 8;                                              \
            int bi = ((s) * 16 + rb) * BST + bcc;                              \
            *(uint4*)(Bs_hi + bi) = vbh[i];                                    \
            *(uint4*)(Bs_lo + bi) = vbl[i];                                    \
        }                                                                      \
    } while (0)

    LD_REGS(0);
    ST_SMEM(0);
    __syncthreads();

    const int nk = K2g >> 4;   // chunks of 16 pairs (32 k)
    for (int t = 0; t < nk; t++) {
        const int cb = t & 1;
        const bool more = (t + 1 < nk);
        if (more) LD_REGS(t + 1);

        #pragma unroll
        for (int kk = 0; kk < 2; kk++) {
            unsigned ah[4][4], al[4][4], bh[4][2], bl[4][2];
            #pragma unroll
            for (int mt = 0; mt < 4; mt++) {
                unsigned off = (((unsigned)(cb * GBM + lrow + mt * 16)) * AST
                                + kk * 8 + lcol) * 4u;
                ldsm_x4(ah[mt], sa_hi + off);
                ldsm_x4(al[mt], sa_lo + off);
            }
            #pragma unroll
            for (int nt = 0; nt < 4; nt++) {
                int cn = wn + nt * 8 + grp;
                int r0 = (cb * 16 + kk * 8 + tig) * BST;
                bh[nt][0] = Bs_hi[r0 + cn];      bh[nt][1] = Bs_hi[r0 + 4 * BST + cn];
                bl[nt][0] = Bs_lo[r0 + cn];      bl[nt][1] = Bs_lo[r0 + 4 * BST + cn];
            }
            #pragma unroll
            for (int mt = 0; mt < 4; mt++)
                #pragma unroll
                for (int nt = 0; nt < 4; nt++) {
                    mma_bf16(c[mt][nt], ah[mt], bl[nt]);
                    mma_bf16(c[mt][nt], al[mt], bh[nt]);
                    mma_bf16(c[mt][nt], ah[mt], bh[nt]);
                }
        }

        if (more) {
            __syncthreads();
            ST_SMEM(1 - cb);
            __syncthreads();
        }
    }

    #pragma unroll
    for (int nt = 0; nt < 4; nt++) {
        int cc = col0 + wn + nt * 8 + 2 * tig;
        float b0 = bias[cc], b1 = bias[cc + 1];
        #pragma unroll
        for (int mt = 0; mt < 4; mt++) {
            int r0 = row0 + wm + mt * 16 + grp;
            if (r0 < M) {
                float v0 = c[mt][nt][0] + b0, v1 = c[mt][nt][1] + b1;
                *(float2*)(C + (size_t)r0 * HID + cc) = make_float2(v0, v1);
                if (do_pack && which == 0) {
                    unsigned hi, lo;
                    split_pack(v0, v1, hi, lo);
                    size_t pi = ((size_t)r0 * HID + cc) >> 1;
                    Pho[pi] = hi; Plo[pi] = lo;
                }
            }
            int r1 = r0 + 8;
            if (r1 < M) {
                float v0 = c[mt][nt][2] + b0, v1 = c[mt][nt][3] + b1;
                *(float2*)(C + (size_t)r1 * HID + cc) = make_float2(v0, v1);
                if (do_pack && which == 0) {
                    unsigned hi, lo;
                    split_pack(v0, v1, hi, lo);
                    size_t pi = ((size_t)r1 * HID + cc) >> 1;
                    Pho[pi] = hi; Plo[pi] = lo;
                }
            }
        }
    }
    #undef LD_REGS
    #undef ST_SMEM
}

// ---------------- CSR build (second stream) ----------------------------------
__global__ void zero_cnt_kernel() {
    int i = blockIdx.x * blockDim.x + threadIdx.x;
    if (i < NN) g_cnt[i] = 0;
}

__global__ void count_kernel(const int* __restrict__ dst) {
    int e = blockIdx.x * blockDim.x + threadIdx.x;
    if (e < NE) atomicAdd(&g_cnt[dst[e]], 1);
}

__global__ __launch_bounds__(1024) void scan_kernel() {
    __shared__ int s[1024];
    int t = threadIdx.x;
    int lo = t * 20;
    int hi = lo + 20; if (hi > NN) hi = NN;
    int sum = 0;
    for (int i = lo; i < hi; i++) sum += g_cnt[i];
    s[t] = sum;
    __syncthreads();
    for (int off = 1; off < 1024; off <<= 1) {
        int v = (t >= off) ? s[t - off] : 0;
        __syncthreads();
        s[t] += v;
        __syncthreads();
    }
    int run = s[t] - sum;
    for (int i = lo; i < hi; i++) {
        g_base[i] = run;
        g_cur[i] = run;
        run += g_cnt[i];
    }
    if (t == 0) g_base[NN] = NE;
}

__global__ void fill_kernel(const int* __restrict__ src, const int* __restrict__ dst) {
    int e = blockIdx.x * blockDim.x + threadIdx.x;
    if (e < NE) {
        int p = atomicAdd(&g_cur[dst[e]], 1);
        g_srcbyd[p] = src[e];
    }
}

__global__ void gbound_kernel(const int* __restrict__ gids) {
    int g = threadIdx.x;
    if (g > NG) return;
    int lo = 0, hi = NN;
    while (lo < hi) {
        int mid = (lo + hi) >> 1;
        if (gids[mid] < g) lo = mid + 1; else hi = mid;
    }
    g_gstart[g] = lo;
}

// ------- fused edge kernel: one warp per NODE, all 8 heads at once -----------
__global__ __launch_bounds__(256) void fused_edge_kernel(const float* __restrict__ attn,
                                                         int do_pack)
{
    int n = blockIdx.x * 8 + (threadIdx.x >> 5);
    int lane = threadIdx.x & 31;
    if (n >= NN) return;
    const size_t rowoff = (size_t)n * HID + lane * 8;

    float fdv[8], av[8];
    {
        float4 t0 = *(const float4*)(g_fd + rowoff);
        float4 t1 = *(const float4*)(g_fd + rowoff + 4);
        fdv[0]=t0.x; fdv[1]=t0.y; fdv[2]=t0.z; fdv[3]=t0.w;
        fdv[4]=t1.x; fdv[5]=t1.y; fdv[6]=t1.z; fdv[7]=t1.w;
        float4 a0 = *(const float4*)(attn + lane * 8);
        float4 a1 = *(const float4*)(attn + lane * 8 + 4);
        av[0]=a0.x; av[1]=a0.y; av[2]=a0.z; av[3]=a0.w;
        av[4]=a1.x; av[5]=a1.y; av[6]=a1.z; av[7]=a1.w;
    }

    const int b  = g_base[n];
    const int e2 = g_base[n + 1];

    float m = -1e30f, sd = 0.f;
    float acc[8] = {0.f,0.f,0.f,0.f,0.f,0.f,0.f,0.f};

    for (int j = b; j < e2; j++) {
        int s = g_srcbyd[j];
        const float4* fp = (const float4*)(g_fs + (size_t)s * HID + lane * 8);
        float4 a0 = fp[0], a1 = fp[1];
        float fsv[8] = {a0.x,a0.y,a0.z,a0.w,a1.x,a1.y,a1.z,a1.w};
        float pp = 0.f;
        #pragma unroll
        for (int q = 0; q < 8; q++) {
            float v = fsv[q] + fdv[q];
            v = (v > 0.f) ? v : SLOPE * v;
            pp = fmaf(v, av[q], pp);
        }
        pp += __shfl_xor_sync(0xffffffffu, pp, 1);
        pp += __shfl_xor_sync(0xffffffffu, pp, 2);
        float nm = fmaxf(m, pp);
        float fac = __expf(m - nm);
        float w   = __expf(pp - nm);
        sd = sd * fac + w;
        #pragma unroll
        for (int q = 0; q < 8; q++) acc[q] = fmaf(acc[q], fac, w * fsv[q]);
        m = nm;
    }

    float inv = (sd > 0.f) ? 1.f / sd : 0.f;
    float hv[8];
    {
        float4 h0 = *(const float4*)(g_h + rowoff);
        float4 h1 = *(const float4*)(g_h + rowoff + 4);
        float hold[8] = {h0.x,h0.y,h0.z,h0.w,h1.x,h1.y,h1.z,h1.w};
        #pragma unroll
        for (int q = 0; q < 8; q++) hv[q] = fmaxf(fmaf(acc[q], inv, hold[q]), 0.f);
    }
    *(float4*)(g_h + rowoff)     = make_float4(hv[0], hv[1], hv[2], hv[3]);
    *(float4*)(g_h + rowoff + 4) = make_float4(hv[4], hv[5], hv[6], hv[7]);
    if (do_pack) {
        size_t pbase = rowoff >> 1;
        #pragma unroll
        for (int q = 0; q < 8; q += 2) {
            unsigned hi, lo;
            split_pack(hv[q], hv[q + 1], hi, lo);
            g_ah_hi[pbase + (q >> 1)] = hi;
            g_ah_lo[pbase + (q >> 1)] = lo;
        }
    }
}

// ---------------- fused pool + 3-layer classifier, one block per graph -------
__global__ __launch_bounds__(256) void poolfc_kernel(
    const float* __restrict__ Wc1, const float* __restrict__ bc1,
    const float* __restrict__ Wc2, const float* __restrict__ bc2,
    const float* __restrict__ Wc3, const float* __restrict__ bc3,
    float* __restrict__ out)
{
    __shared__ float sh[256];
    __shared__ float sx[256];
    int g = blockIdx.x;
    int c = threadIdx.x;
    int n0 = g_gstart[g], n1 = g_gstart[g + 1];
    float s = 0.f;
    for (int n = n0; n < n1; n++) s += g_h[(size_t)n * HID + c];
    sh[c] = s;
    __syncthreads();
    float a = bc1[c];
    #pragma unroll 8
    for (int k = 0; k < HID; k++) a = fmaf(sh[k], Wc1[k * HID + c], a);
    sx[c] = fmaxf(a, 0.f);
    __syncthreads();
    float b2 = 0.f;
    if (c < HID / 2) {
        b2 = bc2[c];
        #pragma unroll 8
        for (int k = 0; k < HID; k++) b2 = fmaf(sx[k], Wc2[k * (HID / 2) + c], b2);
        b2 = fmaxf(b2, 0.f);
    }
    __syncthreads();
    if (c < HID / 2) sh[c] = b2;
    __syncthreads();
    if (c < OUTDIM) {
        float o = bc3[c];
        for (int k = 0; k < HID / 2; k++) o = fmaf(sh[k], Wc3[k * OUTDIM + c], o);
        out[g * OUTDIM + c] = o;
    }
}

// ---------------- launch -------------------------------------------------------
extern "C" void kernel_launch(void* const* d_in, const int* in_sizes, int n_in,
                              void* d_out, int out_size)
{
    const float* feature   = (const float*)d_in[0];
    const float* W_in      = (const float*)d_in[1];
    const float* b_in      = (const float*)d_in[2];
    const float* W_src     = (const float*)d_in[3];
    const float* b_src     = (const float*)d_in[4];
    const float* W_dst     = (const float*)d_in[5];
    const float* b_dst     = (const float*)d_in[6];
    const float* attn      = (const float*)d_in[7];
    const float* Wc1       = (const float*)d_in[8];
    const float* bc1       = (const float*)d_in[9];
    const float* Wc2       = (const float*)d_in[10];
    const float* bc2       = (const float*)d_in[11];
    const float* Wc3       = (const float*)d_in[12];
    const float* bc3       = (const float*)d_in[13];
    const int*   src       = (const int*)d_in[14];
    const int*   dst       = (const int*)d_in[15];
    const int*   graph_ids = (const int*)d_in[16];
    float* out = (float*)d_out;

    float *p_h, *p_fs, *p_fd;
    unsigned *p_ah_hi, *p_ah_lo, *p_af_hi, *p_af_lo;
    unsigned *p_win_hi, *p_win_lo, *p_ws_hi, *p_ws_lo, *p_wd_hi, *p_wd_lo;
    cudaGetSymbolAddress((void**)&p_h,  g_h);
    cudaGetSymbolAddress((void**)&p_fs, g_fs);
    cudaGetSymbolAddress((void**)&p_fd, g_fd);
    cudaGetSymbolAddress((void**)&p_ah_hi, g_ah_hi);
    cudaGetSymbolAddress((void**)&p_ah_lo, g_ah_lo);
    cudaGetSymbolAddress((void**)&p_af_hi, g_af_hi);
    cudaGetSymbolAddress((void**)&p_af_lo, g_af_lo);
    cudaGetSymbolAddress((void**)&p_win_hi, g_win_hi);
    cudaGetSymbolAddress((void**)&p_win_lo, g_win_lo);
    cudaGetSymbolAddress((void**)&p_ws_hi, g_ws_hi);
    cudaGetSymbolAddress((void**)&p_ws_lo, g_ws_lo);
    cudaGetSymbolAddress((void**)&p_wd_hi, g_wd_hi);
    cudaGetSymbolAddress((void**)&p_wd_lo, g_wd_lo);

    cudaFuncSetAttribute(gemm_bf16x3_kernel,
                         cudaFuncAttributeMaxDynamicSharedMemorySize, GSMEM);

    // fork: CSR chain on a second stream, overlapped with pack + GEMM1
    cudaStream_t s2;
    cudaStreamCreateWithFlags(&s2, cudaStreamNonBlocking);
    cudaEvent_t evA, evB;
    cudaEventCreateWithFlags(&evA, cudaEventDisableTiming);
    cudaEventCreateWithFlags(&evB, cudaEventDisableTiming);
    cudaEventRecord(evA, 0);
    cudaStreamWaitEvent(s2, evA, 0);
    zero_cnt_kernel<<<(NN + 255) / 256, 256, 0, s2>>>();
    count_kernel<<<(NE + 255) / 256, 256, 0, s2>>>(dst);
    scan_kernel<<<1, 1024, 0, s2>>>();
    fill_kernel<<<(NE + 255) / 256, 256, 0, s2>>>(src, dst);
    gbound_kernel<<<1, 128, 0, s2>>>(graph_ids);
    cudaEventRecord(evB, s2);

    // main stream: pack, GEMM1
    const int NPACK = NN * K2IN + WIN_P + 2 * LAYERS * WL_P;
    pack_all_kernel<<<(NPACK + 255) / 256, 256>>>(W_in, W_src, W_dst, feature);

    const int MROWS = (NN + GBM - 1) / GBM;
    const int NB = HID / GBN;          // 2 N-tiles per output
    dim3 grid1(NB, MROWS);             // single output
    dim3 grid2(2 * NB, MROWS);         // dual output

    gemm_bf16x3_kernel<<<grid1, 256, GSMEM>>>(
        p_af_hi, p_af_lo, p_win_hi, p_win_lo, p_win_hi, p_win_lo,
        b_in, b_in, p_h, p_h, p_ah_hi, p_ah_lo,
        NN, K2IN, NB, 1);

    // join: edge kernels need the CSR
    cudaStreamWaitEvent(0, evB, 0);

    const int fused_blocks = (NN + 7) / 8;
    for (int l = 0; l < LAYERS; l++) {
        const float* bs = b_src + (size_t)l * HID;
        const float* bd = b_dst + (size_t)l * HID;
        const float* al = attn + (size_t)l * HEADS * DH;

        gemm_bf16x3_kernel<<<grid2, 256, GSMEM>>>(
            p_ah_hi, p_ah_lo,
            p_ws_hi + (size_t)l * WL_P, p_ws_lo + (size_t)l * WL_P,
            p_wd_hi + (size_t)l * WL_P, p_wd_lo + (size_t)l * WL_P,
            bs, bd, p_fs, p_fd, (unsigned*)0, (unsigned*)0,
            NN, K2L, NB, 0);

        fused_edge_kernel<<<fused_blocks, 256>>>(al, (l + 1 < LAYERS) ? 1 : 0);
    }

    poolfc_kernel<<<NG, 256>>>(Wc1, bc1, Wc2, bc2, Wc3, bc3, out);
}